// round 14
// baseline (speedup 1.0000x reference)
#include <cuda_runtime.h>
#include <cuda_bf16.h>
#include <cstdint>
#include <math.h>

// ---------------- problem constants (fixed shapes) ----------------
#define Bz      8
#define NTOK    4096
#define N0      16384
#define NS      16384
#define CC      128
#define HH      64
#define WW      64
#define HWSZ    4096
#define NHEADS  2
#define DH      64
#define M2      256
#define HID     512
#define KSP     8        // split-K factor for SR conv GEMM

// ---------------- packed fp32x2 helpers (attention) ----------------
typedef unsigned long long u64t;
__device__ __forceinline__ u64t dup2(float a) {
    u64t r; asm("mov.b64 %0, {%1, %1};" : "=l"(r) : "f"(a)); return r;
}
__device__ __forceinline__ u64t pack2f(float lo, float hi) {
    u64t r; asm("mov.b64 %0, {%1, %2};" : "=l"(r) : "f"(lo), "f"(hi)); return r;
}
__device__ __forceinline__ void unpack2(u64t v, float& lo, float& hi) {
    asm("mov.b64 {%0, %1}, %2;" : "=f"(lo), "=f"(hi) : "l"(v));
}
__device__ __forceinline__ u64t fma2(u64t a, u64t b, u64t c) {
    u64t d; asm("fma.rn.f32x2 %0, %1, %2, %3;" : "=l"(d) : "l"(a), "l"(b), "l"(c)); return d;
}
__device__ __forceinline__ u64t mul2(u64t a, u64t b) {
    u64t d; asm("mul.rn.f32x2 %0, %1, %2;" : "=l"(d) : "l"(a), "l"(b)); return d;
}
__device__ __forceinline__ u64t add2(u64t a, u64t b) {
    u64t d; asm("add.rn.f32x2 %0, %1, %2;" : "=l"(d) : "l"(a), "l"(b)); return d;
}

// ---------------- mma / ldmatrix / cp.async helpers ----------------
__device__ __forceinline__ void ldsm4(uint32_t& r0, uint32_t& r1, uint32_t& r2, uint32_t& r3,
                                      const void* p) {
    unsigned addr = (unsigned)__cvta_generic_to_shared(p);
    asm volatile("ldmatrix.sync.aligned.m8n8.x4.shared.b16 {%0,%1,%2,%3}, [%4];"
                 : "=r"(r0), "=r"(r1), "=r"(r2), "=r"(r3) : "r"(addr) : "memory");
}
__device__ __forceinline__ void ldsm4t(uint32_t& r0, uint32_t& r1, uint32_t& r2, uint32_t& r3,
                                       const void* p) {
    unsigned addr = (unsigned)__cvta_generic_to_shared(p);
    asm volatile("ldmatrix.sync.aligned.m8n8.x4.trans.shared.b16 {%0,%1,%2,%3}, [%4];"
                 : "=r"(r0), "=r"(r1), "=r"(r2), "=r"(r3) : "r"(addr) : "memory");
}
__device__ __forceinline__ void mma16816(float c[4], const uint32_t a[4], const uint32_t b[2]) {
    asm volatile(
        "mma.sync.aligned.m16n8k16.row.col.f32.bf16.bf16.f32 "
        "{%0,%1,%2,%3}, {%4,%5,%6,%7}, {%8,%9}, {%0,%1,%2,%3};"
        : "+f"(c[0]), "+f"(c[1]), "+f"(c[2]), "+f"(c[3])
        : "r"(a[0]), "r"(a[1]), "r"(a[2]), "r"(a[3]), "r"(b[0]), "r"(b[1]));
}
__device__ __forceinline__ void cp16(void* smem, const void* gmem) {
    unsigned s = (unsigned)__cvta_generic_to_shared(smem);
    asm volatile("cp.async.cg.shared.global [%0], [%1], 16;" :: "r"(s), "l"(gmem) : "memory");
}
#define CP_COMMIT() asm volatile("cp.async.commit_group;" ::: "memory")
#define CP_WAIT(n)  asm volatile("cp.async.wait_group %0;" :: "n"(n) : "memory")

// ---------------- scratch (device globals; no allocation) ----------------
__device__ __align__(16) __nv_bfloat16 g_q [Bz*NTOK*CC];   // bf16 q
__device__ int   g_idx_hw [Bz*N0];

__device__ int   g_cnt_hw [Bz*HWSZ];
__device__ int   g_off_hw [Bz*HWSZ];
__device__ int   g_cnt_n  [Bz*NTOK];
__device__ int   g_off_n  [Bz*NTOK];
// value lists (CSR-ordered consumer data; replaces point-id plists)
__device__ int   g_vhw_src[Bz*N0];   // idx_aggs[p] ordered by hw CSR (t2m1)
__device__ int   g_vhw_agg[Bz*N0];   // idx_agg[p]  ordered by hw CSR (t2m2)
__device__ int   g_vn_hw  [Bz*N0];   // idx_hw[p]   ordered by n CSR  (m2t)
__device__ float g_vn_w   [Bz*N0];   // aggw[p]     ordered by n CSR  (m2t)

__device__ float g_xsmap  [Bz*HWSZ*CC];
__device__ float g_confmap[Bz*HWSZ];
__device__ float g_psum   [KSP*2048*CC];
__device__ float g_confp  [2048];
__device__ float g_kv     [2048*256];
__device__ float g_x1     [Bz*NTOK*CC];
__device__ __align__(16) __nv_bfloat16 g_h     [Bz*NTOK*HID];
__device__ __align__(16) __nv_bfloat16 g_hmap  [Bz*HWSZ*HID];
__device__ __align__(16) __nv_bfloat16 g_hmap2 [Bz*HWSZ*HID];

// bf16 split buffers: A2 max = 32768 x 1024 (fc2); W2 max = 4096 x 256
__device__ __align__(16) __nv_bfloat16 g_a3 [(size_t)32768*1024];
__device__ __align__(16) __nv_bfloat16 g_w3 [(size_t)4096*256];

// ---------------- utility ----------------
__global__ void zero2_kernel(int* __restrict__ p1, int* __restrict__ p2, int n4) {
    int i = blockIdx.x * blockDim.x + threadIdx.x;
    int stride = gridDim.x * blockDim.x;
    int4 z = make_int4(0, 0, 0, 0);
    for (; i < n4; i += stride) { ((int4*)p1)[i] = z; ((int4*)p2)[i] = z; }
}

// ---------------- f32 -> bf16 split helpers ----------------
union BPack { __nv_bfloat16 h[4]; uint2 u; };
__device__ __forceinline__ void split4(float4 v, BPack& hi, BPack& lo) {
    hi.h[0] = __float2bfloat16(v.x); lo.h[0] = __float2bfloat16(v.x - __bfloat162float(hi.h[0]));
    hi.h[1] = __float2bfloat16(v.y); lo.h[1] = __float2bfloat16(v.y - __bfloat162float(hi.h[1]));
    hi.h[2] = __float2bfloat16(v.z); lo.h[2] = __float2bfloat16(v.z - __bfloat162float(hi.h[2]));
    hi.h[3] = __float2bfloat16(v.w); lo.h[3] = __float2bfloat16(v.w - __bfloat162float(hi.h[3]));
}

// LayerNorm fused with 2-segment bf16 split: A2 row = [hi(128) | lo(128)]
__global__ void ln_split_kernel(const float* __restrict__ in, const float* __restrict__ g,
                                const float* __restrict__ b, __nv_bfloat16* __restrict__ a2,
                                int rows) {
    int row  = blockIdx.x * 8 + (threadIdx.x >> 5);
    int lane = threadIdx.x & 31;
    if (row >= rows) return;
    float4 v = ((const float4*)(in + (size_t)row * CC))[lane];
    float s = v.x + v.y + v.z + v.w;
    #pragma unroll
    for (int o = 16; o; o >>= 1) s += __shfl_xor_sync(0xffffffffu, s, o);
    float mean = s * (1.0f / CC);
    float dx = v.x - mean, dy = v.y - mean, dz = v.z - mean, dw = v.w - mean;
    float s2 = dx*dx + dy*dy + dz*dz + dw*dw;
    #pragma unroll
    for (int o = 16; o; o >>= 1) s2 += __shfl_xor_sync(0xffffffffu, s2, o);
    float rstd = rsqrtf(s2 * (1.0f / CC) + 1e-5f);
    float4 gg = ((const float4*)g)[lane];
    float4 bb = ((const float4*)b)[lane];
    float4 o4 = make_float4(dx*rstd*gg.x + bb.x, dy*rstd*gg.y + bb.y,
                            dz*rstd*gg.z + bb.z, dw*rstd*gg.w + bb.w);
    BPack hi, lo;
    split4(o4, hi, lo);
    __nv_bfloat16* base = a2 + (size_t)row * 256;
    *(uint2*)(base + lane*4)        = hi.u;
    *(uint2*)(base + 128 + lane*4)  = lo.u;
}

// split-K reduce + bias + LN(srn) + split (SR conv epilogue)
__global__ void skred_ln_split_kernel(const float* __restrict__ part,
                                      const float* __restrict__ bias,
                                      const float* __restrict__ g, const float* __restrict__ b,
                                      __nv_bfloat16* __restrict__ a2) {
    int row  = blockIdx.x * 8 + (threadIdx.x >> 5);
    int lane = threadIdx.x & 31;
    if (row >= 2048) return;
    const int MN = 2048 * CC;
    float4 v = make_float4(0.f, 0.f, 0.f, 0.f);
    #pragma unroll
    for (int zz = 0; zz < KSP; zz++) {
        float4 p = ((const float4*)(part + (size_t)zz * MN + (size_t)row * CC))[lane];
        v.x += p.x; v.y += p.y; v.z += p.z; v.w += p.w;
    }
    float4 bi = ((const float4*)bias)[lane];
    v.x += bi.x; v.y += bi.y; v.z += bi.z; v.w += bi.w;
    float s = v.x + v.y + v.z + v.w;
    #pragma unroll
    for (int o = 16; o; o >>= 1) s += __shfl_xor_sync(0xffffffffu, s, o);
    float mean = s * (1.0f / CC);
    float dx = v.x - mean, dy = v.y - mean, dz = v.z - mean, dw = v.w - mean;
    float s2 = dx*dx + dy*dy + dz*dz + dw*dw;
    #pragma unroll
    for (int o = 16; o; o >>= 1) s2 += __shfl_xor_sync(0xffffffffu, s2, o);
    float rstd = rsqrtf(s2 * (1.0f / CC) + 1e-5f);
    float4 gg = ((const float4*)g)[lane];
    float4 bb = ((const float4*)b)[lane];
    float4 o4 = make_float4(dx*rstd*gg.x + bb.x, dy*rstd*gg.y + bb.y,
                            dz*rstd*gg.z + bb.z, dw*rstd*gg.w + bb.w);
    BPack hi, lo;
    split4(o4, hi, lo);
    __nv_bfloat16* base = a2 + (size_t)row * 256;
    *(uint2*)(base + lane*4)        = hi.u;
    *(uint2*)(base + 128 + lane*4)  = lo.u;
}

// ---------------- CSR build: grid indices + both counts, one pass ----------------
__global__ void gridcount_kernel(const float* __restrict__ loc, const int* __restrict__ idx_agg,
                                 int* __restrict__ idx_hw,
                                 int* __restrict__ cnt_hw, int* __restrict__ cnt_n) {
    int t = blockIdx.x * blockDim.x + threadIdx.x;
    if (t >= Bz * N0) return;
    int b = t >> 14;
    float2 l = ((const float2*)loc)[t];
    float lx = (fminf(fmaxf(l.x, -1.f), 1.f) + 1.f) * 0.5f;
    float ly = (fminf(fmaxf(l.y, -1.f), 1.f) + 1.f) * 0.5f;
    int xi = (int)rintf(lx * (WW - 1));
    int yi = (int)rintf(ly * (HH - 1));
    int ihw = yi * WW + xi;
    idx_hw[t] = ihw;
    atomicAdd(&cnt_hw[b * HWSZ + ihw], 1);
    atomicAdd(&cnt_n [b * NTOK + idx_agg[t]], 1);
}

// fused scan + fill with value materialization:
// blocks 0..7  -> hw CSR: vhw_src[pos]=idx_aggs[p], vhw_agg[pos]=idx_agg[p]
// blocks 8..15 -> n  CSR: vn_hw[pos]=idx_hw[p], vn_w[pos]=aggw[p]
__global__ __launch_bounds__(1024) void scanfill_kernel(
    const int* __restrict__ cnt_hw, int* __restrict__ off_hw,
    const int* __restrict__ idx_hw, const int* __restrict__ idx_aggs,
    const int* __restrict__ idx_agg,
    int* __restrict__ vhw_src, int* __restrict__ vhw_agg,
    const int* __restrict__ cnt_n, int* __restrict__ off_n,
    const float* __restrict__ aggw,
    int* __restrict__ vn_hw, float* __restrict__ vn_w) {
    __shared__ int sm[1024];
    __shared__ int scur[4096];
    int blk = blockIdx.x, t = threadIdx.x;
    bool is_hw = blk < Bz;
    int b = is_hw ? blk : blk - Bz;
    const int* cnt = is_hw ? cnt_hw : cnt_n;
    int* off = is_hw ? off_hw : off_n;
    const int* c = cnt + b * 4096;
    int v0 = c[t*4], v1 = c[t*4+1], v2 = c[t*4+2], v3 = c[t*4+3];
    int tot = v0 + v1 + v2 + v3;
    sm[t] = tot;
    __syncthreads();
    #pragma unroll
    for (int o = 1; o < 1024; o <<= 1) {
        int u = (t >= o) ? sm[t - o] : 0;
        __syncthreads();
        sm[t] += u;
        __syncthreads();
    }
    int base = sm[t] - tot;
    int* of = off + b * 4096;
    of[t*4]   = base;            scur[t*4]   = base;
    of[t*4+1] = base + v0;       scur[t*4+1] = base + v0;
    of[t*4+2] = base + v0+v1;    scur[t*4+2] = base + v0+v1;
    of[t*4+3] = base + v0+v1+v2; scur[t*4+3] = base + v0+v1+v2;
    __syncthreads();
    if (is_hw) {
        const int* kh = idx_hw  + (size_t)b * N0;
        const int* s1 = idx_aggs + (size_t)b * N0;
        const int* s2 = idx_agg  + (size_t)b * N0;
        int* o1 = vhw_src + (size_t)b * N0;
        int* o2 = vhw_agg + (size_t)b * N0;
        for (int p = t; p < N0; p += 1024) {
            int pos = atomicAdd(&scur[kh[p]], 1);
            o1[pos] = s1[p];
            o2[pos] = s2[p];
        }
    } else {
        const int* kn = idx_agg + (size_t)b * N0;
        const int* s1 = idx_hw  + (size_t)b * N0;
        const float* s2 = aggw  + (size_t)b * N0;
        int* o1 = vn_hw + (size_t)b * N0;
        float* o2 = vn_w + (size_t)b * N0;
        for (int p = t; p < N0; p += 1024) {
            int pos = atomicAdd(&scur[kn[p]], 1);
            o1[pos] = s1[p];
            o2[pos] = s2[p];
        }
    }
}

// ---------------- token2map #1 gather, warp-parallel fused LN, direct value list ----------------
__global__ __launch_bounds__(128) void gather_t2m1_kernel(
    const float* __restrict__ xsrc, const float* __restrict__ confs,
    const float* __restrict__ ln_g, const float* __restrict__ ln_b,
    const int* __restrict__ off_hw, const int* __restrict__ cnt_hw,
    const int* __restrict__ vhw_src,
    float* __restrict__ xsmap, float* __restrict__ confmap) {
    __shared__ float4 s_part[4][32];
    __shared__ float  s_conf[4];
    int cell = blockIdx.x;
    int b = cell >> 12;
    int tid = threadIdx.x;
    int warp = tid >> 5, lane = tid & 31;
    int start = off_hw[cell];
    int n = cnt_hw[cell];
    const int* vl = vhw_src + (size_t)b * N0;
    float4 gg = ((const float4*)ln_g)[lane];
    float4 bb = ((const float4*)ln_b)[lane];
    float4 acc = make_float4(0.f, 0.f, 0.f, 0.f);
    float cs = 0.f;
    for (int j = warp; j < n; j += 4) {
        int i = vl[start + j];
        float4 v = ((const float4*)(xsrc + ((size_t)b * NS + i) * CC))[lane];
        float s1 = v.x + v.y + v.z + v.w;
        float s2 = v.x*v.x + v.y*v.y + v.z*v.z + v.w*v.w;
        #pragma unroll
        for (int o = 16; o; o >>= 1) {
            s1 += __shfl_xor_sync(0xffffffffu, s1, o);
            s2 += __shfl_xor_sync(0xffffffffu, s2, o);
        }
        float mean = s1 * (1.0f / CC);
        float var  = s2 * (1.0f / CC) - mean * mean;
        float rstd = rsqrtf(var + 1e-5f);
        acc.x += (v.x - mean) * rstd * gg.x + bb.x;
        acc.y += (v.y - mean) * rstd * gg.y + bb.y;
        acc.z += (v.z - mean) * rstd * gg.z + bb.z;
        acc.w += (v.w - mean) * rstd * gg.w + bb.w;
        if (lane == 0) cs += confs[(size_t)b * NS + i];
    }
    s_part[warp][lane] = acc;
    if (lane == 0) s_conf[warp] = cs;
    __syncthreads();
    if (tid < 32) {
        float4 a0 = s_part[0][tid], a1 = s_part[1][tid],
               a2 = s_part[2][tid], a3 = s_part[3][tid];
        float inv = 1.0f / fmaxf((float)n, 1.0f);
        float4 o;
        o.x = (a0.x + a1.x + a2.x + a3.x) * inv;
        o.y = (a0.y + a1.y + a2.y + a3.y) * inv;
        o.z = (a0.z + a1.z + a2.z + a3.z) * inv;
        o.w = (a0.w + a1.w + a2.w + a3.w) * inv;
        ((float4*)(xsmap + (size_t)cell * CC))[tid] = o;
        if (tid == 0)
            confmap[cell] = (s_conf[0] + s_conf[1] + s_conf[2] + s_conf[3]) * inv;
    }
}

// ---------------- token2map #2 gather (bf16 h, 512ch) -> bf16 hmap, direct list ----------------
__global__ __launch_bounds__(128) void gather_t2m2_kernel(
    const __nv_bfloat16* __restrict__ h,
    const int* __restrict__ off_hw, const int* __restrict__ cnt_hw,
    const int* __restrict__ vhw_agg, __nv_bfloat16* __restrict__ hmap) {
    __shared__ int s_row[128];
    int cell = blockIdx.x;
    int b = cell >> 12;
    int tid = threadIdx.x;
    int start = off_hw[cell];
    int n = cnt_hw[cell];
    const int* vl = vhw_agg + (size_t)b * N0;
    float4 sum = make_float4(0.f, 0.f, 0.f, 0.f);
    for (int base = 0; base < n; base += 128) {
        int m = min(128, n - base);
        if (tid < m) s_row[tid] = vl[start + base + tid];
        __syncthreads();
        for (int j = 0; j < m; j++) {
            const __nv_bfloat162* vp = (const __nv_bfloat162*)(h +
                ((size_t)b * NTOK + s_row[j]) * HID);
            __nv_bfloat162 p0 = vp[tid*2], p1 = vp[tid*2+1];
            float2 f0 = __bfloat1622float2(p0);
            float2 f1 = __bfloat1622float2(p1);
            sum.x += f0.x; sum.y += f0.y; sum.z += f1.x; sum.w += f1.y;
        }
        __syncthreads();
    }
    float inv = 1.0f / fmaxf((float)n, 1.0f);
    BPack o;
    o.h[0] = __float2bfloat16(sum.x * inv);
    o.h[1] = __float2bfloat16(sum.y * inv);
    o.h[2] = __float2bfloat16(sum.z * inv);
    o.h[3] = __float2bfloat16(sum.w * inv);
    *(uint2*)(hmap + (size_t)cell * HID + tid * 4) = o.u;
}

// ---------------- map2token gather + dwskip + gelu + split -> A2, direct lists ----------------
__global__ __launch_bounds__(128) void gather_m2t_kernel(
    const __nv_bfloat16* __restrict__ hmap2,
    const int* __restrict__ off_n, const int* __restrict__ cnt_n,
    const int* __restrict__ vn_hw, const float* __restrict__ vn_w,
    const __nv_bfloat16* __restrict__ h, const float* __restrict__ skip,
    __nv_bfloat16* __restrict__ a2) {
    __shared__ int   s_hw[128];
    __shared__ float s_w [128];
    int tok = blockIdx.x;
    int b = tok >> 12;
    int tid = threadIdx.x;
    int start = off_n[tok];
    int n = cnt_n[tok];
    const int* vl = vn_hw + (size_t)b * N0;
    const float* wl = vn_w + (size_t)b * N0;
    float4 sum = make_float4(0.f, 0.f, 0.f, 0.f);
    float den = 0.f;
    for (int base = 0; base < n; base += 128) {
        int m = min(128, n - base);
        if (tid < m) {
            s_hw[tid] = vl[start + base + tid];
            s_w[tid]  = wl[start + base + tid];
        }
        __syncthreads();
        for (int j = 0; j < m; j++) {
            float w = s_w[j];
            const __nv_bfloat162* vp = (const __nv_bfloat162*)(hmap2 +
                ((size_t)b * HWSZ + s_hw[j]) * HID);
            __nv_bfloat162 p0 = vp[tid*2], p1 = vp[tid*2+1];
            float2 f0 = __bfloat1622float2(p0);
            float2 f1 = __bfloat1622float2(p1);
            sum.x += w * f0.x; sum.y += w * f0.y; sum.z += w * f1.x; sum.w += w * f1.y;
            den += w;
        }
        __syncthreads();
    }
    float inv = 1.0f / fmaxf(den, 1e-6f);
    const __nv_bfloat162* hp = (const __nv_bfloat162*)(h + (size_t)tok * HID);
    __nv_bfloat162 h0 = hp[tid*2], h1 = hp[tid*2+1];
    float2 hf0 = __bfloat1622float2(h0);
    float2 hf1 = __bfloat1622float2(h1);
    float4 sk = ((const float4*)skip)[tid];
    float4 v;
    v.x = sum.x * inv + hf0.x * sk.x;
    v.y = sum.y * inv + hf0.y * sk.y;
    v.z = sum.z * inv + hf1.x * sk.z;
    v.w = sum.w * inv + hf1.y * sk.w;
    v.x = 0.5f * v.x * (1.0f + erff(v.x * 0.70710678118654752f));
    v.y = 0.5f * v.y * (1.0f + erff(v.y * 0.70710678118654752f));
    v.z = 0.5f * v.z * (1.0f + erff(v.z * 0.70710678118654752f));
    v.w = 0.5f * v.w * (1.0f + erff(v.w * 0.70710678118654752f));
    BPack hi, lo;
    split4(v, hi, lo);
    __nv_bfloat16* base2 = a2 + (size_t)tok * 1024;
    *(uint2*)(base2 + tid*4)        = hi.u;
    *(uint2*)(base2 + 512 + tid*4)  = lo.u;
}

__global__ void confp_kernel(const float* __restrict__ conf_map, float* __restrict__ confp) {
    int t = blockIdx.x * blockDim.x + threadIdx.x;
    if (t >= Bz * M2) return;
    int b = t >> 8;
    int p = t & 255;
    int oy = p >> 4, ox = p & 15;
    float s = 0.f;
    #pragma unroll
    for (int i = 0; i < 4; i++)
        #pragma unroll
        for (int j = 0; j < 4; j++)
            s += conf_map[b * HWSZ + (oy * 4 + i) * WW + (ox * 4 + j)];
    confp[t] = s * (1.0f / 16.0f);
}

// W [K][N] f32 -> W2 [2K][N] bf16: rows [whi | wlo]
__global__ void conv3_W_kernel(const float* __restrict__ in, __nv_bfloat16* __restrict__ out,
                               int K, int N) {
    int t = blockIdx.x * blockDim.x + threadIdx.x;
    int nq = N >> 2;
    if (t >= K * nq) return;
    int k = t / nq, n4 = t - k * nq;
    float4 v = ((const float4*)in)[t];
    BPack hi, lo;
    split4(v, hi, lo);
    *(uint2*)(out + (size_t)k*N + n4*4)        = hi.u;
    *(uint2*)(out + (size_t)(K + k)*N + n4*4)  = lo.u;
}

// im2col fused with split: A2 [2048][4096] = [hi(2048)|lo(2048)]
__global__ void im2col3_kernel(const float* __restrict__ xs_map, __nv_bfloat16* __restrict__ A2) {
    int t = blockIdx.x * blockDim.x + threadIdx.x;
    if (t >= 2048 * 512) return;
    int p   = t >> 9;
    int q   = t & 511;
    int kpos = q >> 5;
    int ci4  = q & 31;
    int ky = kpos >> 2, kx = kpos & 3;
    int b = p >> 8;
    int rem = p & 255;
    int oy = rem >> 4, ox = rem & 15;
    float4 v = *(const float4*)(xs_map +
        (((size_t)b * HWSZ + (oy * 4 + ky) * WW + (ox * 4 + kx)) * CC) + ci4 * 4);
    BPack hi, lo;
    split4(v, hi, lo);
    __nv_bfloat16* base = A2 + (size_t)p * 4096;
    *(uint2*)(base + q*4)          = hi.u;
    *(uint2*)(base + 2048 + q*4)   = lo.u;
}

// ---------------- pipelined bf16 HMMA GEMM (3-stage, wrap-indexed 3-term) ----------------
#define AS_STRIDE 56
#define BS_STRIDE 136
#define AS_ELEMS  (128 * AS_STRIDE)
#define BS_ELEMS  (32 * BS_STRIDE)
#define HG_SMEM   (3 * (AS_ELEMS + BS_ELEMS) * 2)
__global__ __launch_bounds__(256, 2) void hgemm_kernel(
    const __nv_bfloat16* __restrict__ A, const __nv_bfloat16* __restrict__ B,
    const float* __restrict__ bias, const float* __restrict__ res,
    float* __restrict__ C, __nv_bfloat16* __restrict__ Cbf,
    int M, int N, int K, int KS) {
    extern __shared__ __align__(16) __nv_bfloat16 smbuf[];
    __nv_bfloat16* As0 = smbuf;
    __nv_bfloat16* Bs0 = smbuf + 3 * AS_ELEMS;
    int bm = blockIdx.y * 128;
    int bn = blockIdx.x * 128;
    int z  = blockIdx.z;
    int tid = threadIdx.x, lane = tid & 31, wid = tid >> 5;
    int wm = (wid >> 2) * 64, wn = (wid & 3) * 32;
    int K2 = 2 * K;

    float c[4][4][4];
    #pragma unroll
    for (int mt = 0; mt < 4; mt++)
        #pragma unroll
        for (int nt = 0; nt < 4; nt++)
            #pragma unroll
            for (int i = 0; i < 4; i++) c[mt][nt][i] = 0.f;

    int arow0 = tid >> 2, ach = tid & 3;
    int NIT = KS / 32;
    int kbase = z * KS;

    auto load_stage = [&](int st, int k0) {
        int ka = (k0 < K2) ? k0 : k0 - K2;
        int kb = (k0 < K)  ? k0 : k0 - K;
        __nv_bfloat16* Asp = As0 + st * AS_ELEMS;
        __nv_bfloat16* Bsp = Bs0 + st * BS_ELEMS;
        #pragma unroll
        for (int i = 0; i < 2; i++) {
            int row = arow0 + i * 64;
            cp16(&Asp[row * AS_STRIDE + ach * 8],
                 &A[(size_t)(bm + row) * K2 + ka + ach * 8]);
        }
        #pragma unroll
        for (int j = 0; j < 2; j++) {
            int idx = tid + j * 256;
            int row = idx >> 4, ch = idx & 15;
            cp16(&Bsp[row * BS_STRIDE + ch * 8],
                 &B[(size_t)(kb + row) * N + bn + ch * 8]);
        }
    };

    load_stage(0, kbase);
    CP_COMMIT();
    load_stage(1, kbase + 32);
    CP_COMMIT();

    for (int it = 0; it < NIT; it++) {
        CP_WAIT(1);
        __syncthreads();
        int st = it % 3;
        const __nv_bfloat16* Asp = As0 + st * AS_ELEMS;
        const __nv_bfloat16* Bsp = Bs0 + st * BS_ELEMS;
        #pragma unroll
        for (int ks = 0; ks < 2; ks++) {
            uint32_t a[4][4];
            #pragma unroll
            for (int mt = 0; mt < 4; mt++) {
                const void* p = &Asp[(wm + mt*16 + (lane & 15)) * AS_STRIDE + ks*16 + (lane >> 4) * 8];
                ldsm4(a[mt][0], a[mt][1], a[mt][2], a[mt][3], p);
            }
            uint32_t bfr[4][2];
            #pragma unroll
            for (int np = 0; np < 2; np++) {
                int g = lane >> 3, r = lane & 7;
                const void* p = &Bsp[(ks*16 + (g & 1)*8 + r) * BS_STRIDE + wn + np*16 + (g >> 1) * 8];
                uint32_t r0, r1, r2, r3;
                ldsm4t(r0, r1, r2, r3, p);
                bfr[np*2][0] = r0;   bfr[np*2][1] = r1;
                bfr[np*2+1][0] = r2; bfr[np*2+1][1] = r3;
            }
            #pragma unroll
            for (int mt = 0; mt < 4; mt++)
                #pragma unroll
                for (int nt = 0; nt < 4; nt++)
                    mma16816(c[mt][nt], a[mt], bfr[nt]);
        }
        __syncthreads();
        if (it + 2 < NIT) load_stage((it + 2) % 3, kbase + (it + 2) * 32);
        CP_COMMIT();
    }

    int r0 = lane >> 2, cc = (lane & 3) * 2;
    float* Cz = C ? (C + (size_t)z * M * N) : nullptr;
    #pragma unroll
    for (int mt = 0; mt < 4; mt++) {
        #pragma unroll
        for (int nt = 0; nt < 4; nt++) {
            int row = bm + wm + mt*16 + r0;
            int col = bn + wn + nt*8 + cc;
            float2 v0 = make_float2(c[mt][nt][0], c[mt][nt][1]);
            float2 v1 = make_float2(c[mt][nt][2], c[mt][nt][3]);
            if (bias) {
                float b0 = bias[col], b1 = bias[col+1];
                v0.x += b0; v0.y += b1; v1.x += b0; v1.y += b1;
            }
            size_t off0 = (size_t)row * N + col;
            size_t off1 = (size_t)(row + 8) * N + col;
            if (Cbf) {
                __nv_bfloat162 o0 = __floats2bfloat162_rn(v0.x, v0.y);
                __nv_bfloat162 o1 = __floats2bfloat162_rn(v1.x, v1.y);
                *(__nv_bfloat162*)(Cbf + off0) = o0;
                *(__nv_bfloat162*)(Cbf + off1) = o1;
            } else {
                if (res) {
                    float2 rr0 = *(const float2*)(res + off0);
                    float2 rr1 = *(const float2*)(res + off1);
                    v0.x += rr0.x; v0.y += rr0.y; v1.x += rr1.x; v1.y += rr1.y;
                }
                *(float2*)(Cz + off0) = v0;
                *(float2*)(Cz + off1) = v1;
            }
        }
    }
}

// ---------------- fused attention: unshifted softmax + f32x2, bf16 q, 256 thr ----------------
__global__ __launch_bounds__(256) void attn_kernel(
    const __nv_bfloat16* __restrict__ q, const float* __restrict__ kv,
    const float* __restrict__ confp, __nv_bfloat16* __restrict__ a2) {
    extern __shared__ float sm[];
    float* ks = sm;
    float* vs = sm + M2 * DH;
    float* cp = sm + 2 * M2 * DH;
    int bh = blockIdx.y;
    int b = bh >> 1, h = bh & 1;
    int tid = threadIdx.x;
    for (int t = tid; t < M2 * 16; t += 256) {
        int m = t >> 4, j4 = t & 15;
        const float* row = kv + ((size_t)(b * M2 + m)) * 256;
        ((float4*)ks)[m * 16 + j4] = ((const float4*)(row + h * DH))[j4];
        ((float4*)vs)[m * 16 + j4] = ((const float4*)(row + 128 + h * DH))[j4];
    }
    for (int t = tid; t < M2; t += 256) cp[t] = confp[b * M2 + t];
    __syncthreads();

    int n = blockIdx.x * 256 + tid;
    const __nv_bfloat162* qp = (const __nv_bfloat162*)(q + ((size_t)(b * NTOK + n)) * CC + h * DH);
    u64t q2[32];
    #pragma unroll
    for (int t = 0; t < 32; t++) {
        float2 f = __bfloat1622float2(qp[t]);
        q2[t] = pack2f(f.x * 0.125f, f.y * 0.125f);
    }
    u64t acc2[32];
    #pragma unroll
    for (int j = 0; j < 32; j++) acc2[j] = 0ULL;
    float l = 0.f;

    for (int m = 0; m < M2; m++) {
        const ulonglong2* kp = (const ulonglong2*)(ks + m * DH);
        u64t s0 = 0ULL, s1 = 0ULL, s2 = 0ULL, s3 = 0ULL;
        #pragma unroll
        for (int t = 0; t < 16; t += 2) {
            ulonglong2 k0 = kp[t];
            ulonglong2 k1 = kp[t+1];
            s0 = fma2(q2[2*t],   k0.x, s0);
            s1 = fma2(q2[2*t+1], k0.y, s1);
            s2 = fma2(q2[2*t+2], k1.x, s2);
            s3 = fma2(q2[2*t+3], k1.y, s3);
        }
        u64t st = add2(add2(s0, s1), add2(s2, s3));
        float slo, shi;
        unpack2(st, slo, shi);
        float p = __expf(slo + shi + cp[m]);
        l += p;
        u64t p2 = dup2(p);
        const ulonglong2* vp = (const ulonglong2*)(vs + m * DH);
        #pragma unroll
        for (int t = 0; t < 16; t++) {
            ulonglong2 vv = vp[t];
            acc2[2*t]   = fma2(p2, vv.x, acc2[2*t]);
            acc2[2*t+1] = fma2(p2, vv.y, acc2[2*t+1]);
        }
    }
    float inv = 1.0f / l;
    __nv_bfloat16* a2row = a2 + (size_t)(b * NTOK + n) * 256 + h * DH;
    #pragma unroll
    for (int t = 0; t < 16; t++) {
        float c0, c1, c2, c3;
        unpack2(acc2[2*t], c0, c1);
        unpack2(acc2[2*t+1], c2, c3);
        float4 o4 = make_float4(c0 * inv, c1 * inv, c2 * inv, c3 * inv);
        BPack hi, lo;
        split4(o4, hi, lo);
        *(uint2*)(a2row + t*4)        = hi.u;
        *(uint2*)(a2row + 128 + t*4)  = lo.u;
    }
}

// depthwise 3x3 SAME conv over (B,64,64,512), bf16 in / bf16 out
__global__ void dwconv_kernel(const __nv_bfloat16* __restrict__ hmap, const float* __restrict__ w,
                              const float* __restrict__ bias, __nv_bfloat16* __restrict__ out) {
    __shared__ float ws[9 * HID];
    __shared__ float bs[HID];
    int b = blockIdx.y, y = blockIdx.x;
    for (int t = threadIdx.x; t < 9 * HID; t += blockDim.x) ws[t] = w[t];
    for (int t = threadIdx.x; t < HID; t += blockDim.x) bs[t] = bias[t];
    __syncthreads();
    const __nv_bfloat16* base = hmap + ((size_t)b * HWSZ) * HID;
    __nv_bfloat16* ob = out + ((size_t)(b * HWSZ) + y * WW) * HID;
    const int H2 = HID / 2;
    for (int t = threadIdx.x; t < WW * H2; t += blockDim.x) {
        int x = t / H2;
        int c2 = t - x * H2;
        int c = c2 * 2;
        float accx = bs[c], accy = bs[c + 1];
        #pragma unroll
        for (int dy = -1; dy <= 1; dy++) {
            int yy = y + dy;
            if ((unsigned)yy >= HH) continue;
            #pragma unroll
            for (int dx = -1; dx <= 1; dx++) {
                int xx = x + dx;
                if ((unsigned)xx >= WW) continue;
                __nv_bfloat162 p = *(const __nv_bfloat162*)(base +
                    ((size_t)(yy * WW + xx)) * HID + c);
                float2 f = __bfloat1622float2(p);
                int wi = ((dy+1)*3 + dx+1) * HID + c;
                accx += f.x * ws[wi];
                accy += f.y * ws[wi + 1];
            }
        }
        *(__nv_bfloat162*)(ob + (size_t)x * HID + c) = __floats2bfloat162_rn(accx, accy);
    }
}

// ---------------- host helpers ----------------
static __nv_bfloat16 *s_a3, *s_w3;

static void hgemm_run(const float* W, const float* bias, const float* res,
                      float* C, __nv_bfloat16* Cbf, int M, int Nc, int K) {
    conv3_W_kernel<<<(K * Nc / 4 + 255) / 256, 256>>>(W, s_w3, K, Nc);
    cudaFuncSetAttribute(hgemm_kernel, cudaFuncAttributeMaxDynamicSharedMemorySize, HG_SMEM);
    dim3 grid(Nc / 128, M / 128, 1);
    hgemm_kernel<<<grid, 256, HG_SMEM>>>(s_a3, s_w3, bias, res, C, Cbf, M, Nc, K, 3 * K);
}

extern "C" void kernel_launch(void* const* d_in, const int* in_sizes, int n_in,
                              void* d_out, int out_size) {
    const float* x        = (const float*)d_in[0];
    const float* loc      = (const float*)d_in[1];
    const int*   idx_agg  = (const int*)  d_in[2];
    const float* aggw     = (const float*)d_in[3];
    const float* xsrc     = (const float*)d_in[4];
    const int*   idx_aggs = (const int*)  d_in[5];
    const float* confs    = (const float*)d_in[6];
    const float* ln1_g    = (const float*)d_in[7];
    const float* ln1_b    = (const float*)d_in[8];
    const float* ln2_g    = (const float*)d_in[9];
    const float* ln2_b    = (const float*)d_in[10];
    const float* wq       = (const float*)d_in[11];
    const float* wkv      = (const float*)d_in[12];
    const float* wproj    = (const float*)d_in[13];
    const float* bproj    = (const float*)d_in[14];
    const float* sr_w     = (const float*)d_in[15];
    const float* sr_b     = (const float*)d_in[16];
    const float* srn_g    = (const float*)d_in[17];
    const float* srn_b    = (const float*)d_in[18];
    const float* fc1_w    = (const float*)d_in[19];
    const float* fc1_b    = (const float*)d_in[20];
    const float* dw_w     = (const float*)d_in[21];
    const float* dw_b     = (const float*)d_in[22];
    const float* dwskip   = (const float*)d_in[23];
    const float* fc2_w    = (const float*)d_in[24];
    const float* fc2_b    = (const float*)d_in[25];
    float* out = (float*)d_out;

    float *p_xsmap, *p_confmap, *p_psum, *p_confp, *p_kv, *p_x1, *p_vn_w;
    __nv_bfloat16 *p_q, *p_h, *p_hmap, *p_hmap2;
    int *p_idx_hw, *p_cnt_hw, *p_off_hw, *p_cnt_n, *p_off_n,
        *p_vhw_src, *p_vhw_agg, *p_vn_hw;
    cudaGetSymbolAddress((void**)&p_q, g_q);
    cudaGetSymbolAddress((void**)&p_idx_hw, g_idx_hw);
    cudaGetSymbolAddress((void**)&p_cnt_hw, g_cnt_hw);
    cudaGetSymbolAddress((void**)&p_off_hw, g_off_hw);
    cudaGetSymbolAddress((void**)&p_cnt_n, g_cnt_n);
    cudaGetSymbolAddress((void**)&p_off_n, g_off_n);
    cudaGetSymbolAddress((void**)&p_vhw_src, g_vhw_src);
    cudaGetSymbolAddress((void**)&p_vhw_agg, g_vhw_agg);
    cudaGetSymbolAddress((void**)&p_vn_hw, g_vn_hw);
    cudaGetSymbolAddress((void**)&p_vn_w, g_vn_w);
    cudaGetSymbolAddress((void**)&p_xsmap, g_xsmap);
    cudaGetSymbolAddress((void**)&p_confmap, g_confmap);
    cudaGetSymbolAddress((void**)&p_psum, g_psum);
    cudaGetSymbolAddress((void**)&p_confp, g_confp);
    cudaGetSymbolAddress((void**)&p_kv, g_kv);
    cudaGetSymbolAddress((void**)&p_x1, g_x1);
    cudaGetSymbolAddress((void**)&p_h, g_h);
    cudaGetSymbolAddress((void**)&p_hmap, g_hmap);
    cudaGetSymbolAddress((void**)&p_hmap2, g_hmap2);
    cudaGetSymbolAddress((void**)&s_a3, g_a3);
    cudaGetSymbolAddress((void**)&s_w3, g_w3);

    // 1. CSR build: zero -> fused grid+count -> fused scan+fill (value lists)
    zero2_kernel<<<32, 256>>>(p_cnt_hw, p_cnt_n, Bz*HWSZ/4);
    gridcount_kernel<<<(Bz*N0 + 255) / 256, 256>>>(loc, idx_agg, p_idx_hw, p_cnt_hw, p_cnt_n);
    scanfill_kernel<<<16, 1024>>>(p_cnt_hw, p_off_hw, p_idx_hw, idx_aggs, idx_agg,
                                  p_vhw_src, p_vhw_agg,
                                  p_cnt_n, p_off_n, aggw, p_vn_hw, p_vn_w);

    // 2. token2map #1, warp-parallel fused LN, direct value list
    gather_t2m1_kernel<<<Bz*HWSZ, 128>>>(xsrc, confs, ln1_g, ln1_b,
                                         p_off_hw, p_cnt_hw, p_vhw_src,
                                         p_xsmap, p_confmap);

    // 3. SR conv
    im2col3_kernel<<<(2048*512 + 255) / 256, 256>>>(p_xsmap, s_a3);
    conv3_W_kernel<<<(2048*128/4 + 255) / 256, 256>>>(sr_w, s_w3, 2048, 128);
    {
        cudaFuncSetAttribute(hgemm_kernel, cudaFuncAttributeMaxDynamicSharedMemorySize, HG_SMEM);
        dim3 grid(1, 16, KSP);
        hgemm_kernel<<<grid, 256, HG_SMEM>>>(s_a3, s_w3, nullptr, nullptr, p_psum, nullptr,
                                             2048, 128, 2048, 6144 / KSP);
    }

    // 4. conf pooling
    confp_kernel<<<(Bz*M2 + 255) / 256, 256>>>(p_confmap, p_confp);

    // 5a. reduce+LN(srn)+split -> a2; wkv GEMM
    skred_ln_split_kernel<<<(2048 + 7) / 8, 256>>>(p_psum, sr_b, srn_g, srn_b, s_a3);
    hgemm_run(wkv, nullptr, nullptr, p_kv, nullptr, 2048, 256, 128);

    // 5b. LN(ln1,x)+split -> a2; wq GEMM (bf16 q out)
    ln_split_kernel<<<(Bz*NTOK + 7) / 8, 256>>>(x, ln1_g, ln1_b, s_a3, Bz*NTOK);
    hgemm_run(wq, nullptr, nullptr, nullptr, p_q, Bz*NTOK, 128, 128);

    // 6. fused attention
    {
        size_t smem = (2 * M2 * DH + M2) * sizeof(float);
        cudaFuncSetAttribute(attn_kernel, cudaFuncAttributeMaxDynamicSharedMemorySize, (int)smem);
        dim3 grid(NTOK / 256, Bz * NHEADS);
        attn_kernel<<<grid, 256, smem>>>(p_q, p_kv, p_confp, s_a3);
    }

    // 7. output projection + residual
    hgemm_run(wproj, bproj, x, p_x1, nullptr, Bz*NTOK, 128, 128);

    // 8. ln2+split + fc1 (bf16 h out)
    ln_split_kernel<<<(Bz*NTOK + 7) / 8, 256>>>(p_x1, ln2_g, ln2_b, s_a3, Bz*NTOK);
    hgemm_run(fc1_w, fc1_b, nullptr, nullptr, p_h, Bz*NTOK, 512, 128);

    // 9. token2map #2, direct value list
    gather_t2m2_kernel<<<Bz*HWSZ, 128>>>(p_h, p_off_hw, p_cnt_hw, p_vhw_agg, p_hmap);

    // 10. depthwise 3x3 SAME conv
    {
        dim3 grid(HH, Bz);
        dwconv_kernel<<<grid, 256>>>(p_hmap, dw_w, dw_b, p_hmap2);
    }

    // 11. map2token + dwskip + gelu + split -> a2, direct value lists
    gather_m2t_kernel<<<Bz*NTOK, 128>>>(p_hmap2, p_off_n, p_cnt_n, p_vn_hw, p_vn_w,
                                        p_h, dwskip, s_a3);

    // 12. fc2 + residual -> output
    hgemm_run(fc2_w, fc2_b, p_x1, out, nullptr, Bz*NTOK, 128, 512);
}

// round 15
// speedup vs baseline: 1.0237x; 1.0237x over previous
#include <cuda_runtime.h>
#include <cuda_bf16.h>
#include <cstdint>
#include <math.h>

// ---------------- problem constants (fixed shapes) ----------------
#define Bz      8
#define NTOK    4096
#define N0      16384
#define NS      16384
#define CC      128
#define HH      64
#define WW      64
#define HWSZ    4096
#define NHEADS  2
#define DH      64
#define M2      256
#define HID     512
#define KSP     8        // split-K factor for SR conv GEMM

// ---------------- packed fp32x2 helpers (attention) ----------------
typedef unsigned long long u64t;
__device__ __forceinline__ u64t dup2(float a) {
    u64t r; asm("mov.b64 %0, {%1, %1};" : "=l"(r) : "f"(a)); return r;
}
__device__ __forceinline__ u64t pack2f(float lo, float hi) {
    u64t r; asm("mov.b64 %0, {%1, %2};" : "=l"(r) : "f"(lo), "f"(hi)); return r;
}
__device__ __forceinline__ void unpack2(u64t v, float& lo, float& hi) {
    asm("mov.b64 {%0, %1}, %2;" : "=f"(lo), "=f"(hi) : "l"(v));
}
__device__ __forceinline__ u64t fma2(u64t a, u64t b, u64t c) {
    u64t d; asm("fma.rn.f32x2 %0, %1, %2, %3;" : "=l"(d) : "l"(a), "l"(b), "l"(c)); return d;
}
__device__ __forceinline__ u64t mul2(u64t a, u64t b) {
    u64t d; asm("mul.rn.f32x2 %0, %1, %2;" : "=l"(d) : "l"(a), "l"(b)); return d;
}
__device__ __forceinline__ u64t add2(u64t a, u64t b) {
    u64t d; asm("add.rn.f32x2 %0, %1, %2;" : "=l"(d) : "l"(a), "l"(b)); return d;
}

// ---------------- mma / ldmatrix / cp.async helpers ----------------
__device__ __forceinline__ void ldsm4(uint32_t& r0, uint32_t& r1, uint32_t& r2, uint32_t& r3,
                                      const void* p) {
    unsigned addr = (unsigned)__cvta_generic_to_shared(p);
    asm volatile("ldmatrix.sync.aligned.m8n8.x4.shared.b16 {%0,%1,%2,%3}, [%4];"
                 : "=r"(r0), "=r"(r1), "=r"(r2), "=r"(r3) : "r"(addr) : "memory");
}
__device__ __forceinline__ void ldsm4t(uint32_t& r0, uint32_t& r1, uint32_t& r2, uint32_t& r3,
                                       const void* p) {
    unsigned addr = (unsigned)__cvta_generic_to_shared(p);
    asm volatile("ldmatrix.sync.aligned.m8n8.x4.trans.shared.b16 {%0,%1,%2,%3}, [%4];"
                 : "=r"(r0), "=r"(r1), "=r"(r2), "=r"(r3) : "r"(addr) : "memory");
}
__device__ __forceinline__ void mma16816(float c[4], const uint32_t a[4], const uint32_t b[2]) {
    asm volatile(
        "mma.sync.aligned.m16n8k16.row.col.f32.bf16.bf16.f32 "
        "{%0,%1,%2,%3}, {%4,%5,%6,%7}, {%8,%9}, {%0,%1,%2,%3};"
        : "+f"(c[0]), "+f"(c[1]), "+f"(c[2]), "+f"(c[3])
        : "r"(a[0]), "r"(a[1]), "r"(a[2]), "r"(a[3]), "r"(b[0]), "r"(b[1]));
}
__device__ __forceinline__ void cp16(void* smem, const void* gmem) {
    unsigned s = (unsigned)__cvta_generic_to_shared(smem);
    asm volatile("cp.async.cg.shared.global [%0], [%1], 16;" :: "r"(s), "l"(gmem) : "memory");
}
#define CP_COMMIT() asm volatile("cp.async.commit_group;" ::: "memory")
#define CP_WAIT(n)  asm volatile("cp.async.wait_group %0;" :: "n"(n) : "memory")

// ---------------- scratch (device globals; no allocation) ----------------
__device__ __align__(16) __nv_bfloat16 g_q [Bz*NTOK*CC];   // bf16 q
__device__ int   g_idx_hw [Bz*N0];

__device__ int   g_cnt_hw [Bz*HWSZ];
__device__ int   g_off_hw [Bz*HWSZ];
__device__ int   g_cnt_n  [Bz*NTOK];
__device__ int   g_off_n  [Bz*NTOK];
// value lists (CSR-ordered consumer data)
__device__ int   g_vhw_src[Bz*N0];   // idx_aggs[p] ordered by hw CSR (t2m1)
__device__ int   g_vhw_agg[Bz*N0];   // idx_agg[p]  ordered by hw CSR (t2m2)
__device__ int   g_vn_hw  [Bz*N0];   // idx_hw[p]   ordered by n CSR  (m2t)
__device__ float g_vn_w   [Bz*N0];   // aggw[p]     ordered by n CSR  (m2t)

__device__ float g_confmap[Bz*HWSZ];
__device__ float g_psum   [KSP*2048*CC];
__device__ float g_confp  [2048];
__device__ float g_kv     [2048*256];
__device__ float g_x1     [Bz*NTOK*CC];
__device__ __align__(16) __nv_bfloat16 g_h     [Bz*NTOK*HID];
__device__ __align__(16) __nv_bfloat16 g_hmap  [Bz*HWSZ*HID];
__device__ __align__(16) __nv_bfloat16 g_hmap2 [Bz*HWSZ*HID];

// bf16 split buffers: A2 max = 32768 x 1024 (fc2); W2 max = 4096 x 256
__device__ __align__(16) __nv_bfloat16 g_a3 [(size_t)32768*1024];
__device__ __align__(16) __nv_bfloat16 g_w3 [(size_t)4096*256];

// ---------------- utility ----------------
__global__ void zero2_kernel(int* __restrict__ p1, int* __restrict__ p2, int n4) {
    int i = blockIdx.x * blockDim.x + threadIdx.x;
    int stride = gridDim.x * blockDim.x;
    int4 z = make_int4(0, 0, 0, 0);
    for (; i < n4; i += stride) { ((int4*)p1)[i] = z; ((int4*)p2)[i] = z; }
}

// ---------------- f32 -> bf16 split helpers ----------------
union BPack { __nv_bfloat16 h[4]; uint2 u; };
__device__ __forceinline__ void split4(float4 v, BPack& hi, BPack& lo) {
    hi.h[0] = __float2bfloat16(v.x); lo.h[0] = __float2bfloat16(v.x - __bfloat162float(hi.h[0]));
    hi.h[1] = __float2bfloat16(v.y); lo.h[1] = __float2bfloat16(v.y - __bfloat162float(hi.h[1]));
    hi.h[2] = __float2bfloat16(v.z); lo.h[2] = __float2bfloat16(v.z - __bfloat162float(hi.h[2]));
    hi.h[3] = __float2bfloat16(v.w); lo.h[3] = __float2bfloat16(v.w - __bfloat162float(hi.h[3]));
}

// LayerNorm fused with 2-segment bf16 split: A2 row = [hi(128) | lo(128)]
__global__ void ln_split_kernel(const float* __restrict__ in, const float* __restrict__ g,
                                const float* __restrict__ b, __nv_bfloat16* __restrict__ a2,
                                int rows) {
    int row  = blockIdx.x * 8 + (threadIdx.x >> 5);
    int lane = threadIdx.x & 31;
    if (row >= rows) return;
    float4 v = ((const float4*)(in + (size_t)row * CC))[lane];
    float s = v.x + v.y + v.z + v.w;
    #pragma unroll
    for (int o = 16; o; o >>= 1) s += __shfl_xor_sync(0xffffffffu, s, o);
    float mean = s * (1.0f / CC);
    float dx = v.x - mean, dy = v.y - mean, dz = v.z - mean, dw = v.w - mean;
    float s2 = dx*dx + dy*dy + dz*dz + dw*dw;
    #pragma unroll
    for (int o = 16; o; o >>= 1) s2 += __shfl_xor_sync(0xffffffffu, s2, o);
    float rstd = rsqrtf(s2 * (1.0f / CC) + 1e-5f);
    float4 gg = ((const float4*)g)[lane];
    float4 bb = ((const float4*)b)[lane];
    float4 o4 = make_float4(dx*rstd*gg.x + bb.x, dy*rstd*gg.y + bb.y,
                            dz*rstd*gg.z + bb.z, dw*rstd*gg.w + bb.w);
    BPack hi, lo;
    split4(o4, hi, lo);
    __nv_bfloat16* base = a2 + (size_t)row * 256;
    *(uint2*)(base + lane*4)        = hi.u;
    *(uint2*)(base + 128 + lane*4)  = lo.u;
}

// split-K reduce + bias + LN(srn) + split (SR conv epilogue)
__global__ void skred_ln_split_kernel(const float* __restrict__ part,
                                      const float* __restrict__ bias,
                                      const float* __restrict__ g, const float* __restrict__ b,
                                      __nv_bfloat16* __restrict__ a2) {
    int row  = blockIdx.x * 8 + (threadIdx.x >> 5);
    int lane = threadIdx.x & 31;
    if (row >= 2048) return;
    const int MN = 2048 * CC;
    float4 v = make_float4(0.f, 0.f, 0.f, 0.f);
    #pragma unroll
    for (int zz = 0; zz < KSP; zz++) {
        float4 p = ((const float4*)(part + (size_t)zz * MN + (size_t)row * CC))[lane];
        v.x += p.x; v.y += p.y; v.z += p.z; v.w += p.w;
    }
    float4 bi = ((const float4*)bias)[lane];
    v.x += bi.x; v.y += bi.y; v.z += bi.z; v.w += bi.w;
    float s = v.x + v.y + v.z + v.w;
    #pragma unroll
    for (int o = 16; o; o >>= 1) s += __shfl_xor_sync(0xffffffffu, s, o);
    float mean = s * (1.0f / CC);
    float dx = v.x - mean, dy = v.y - mean, dz = v.z - mean, dw = v.w - mean;
    float s2 = dx*dx + dy*dy + dz*dz + dw*dw;
    #pragma unroll
    for (int o = 16; o; o >>= 1) s2 += __shfl_xor_sync(0xffffffffu, s2, o);
    float rstd = rsqrtf(s2 * (1.0f / CC) + 1e-5f);
    float4 gg = ((const float4*)g)[lane];
    float4 bb = ((const float4*)b)[lane];
    float4 o4 = make_float4(dx*rstd*gg.x + bb.x, dy*rstd*gg.y + bb.y,
                            dz*rstd*gg.z + bb.z, dw*rstd*gg.w + bb.w);
    BPack hi, lo;
    split4(o4, hi, lo);
    __nv_bfloat16* base = a2 + (size_t)row * 256;
    *(uint2*)(base + lane*4)        = hi.u;
    *(uint2*)(base + 128 + lane*4)  = lo.u;
}

// ---------------- CSR build: grid indices + both counts, one pass ----------------
__global__ void gridcount_kernel(const float* __restrict__ loc, const int* __restrict__ idx_agg,
                                 int* __restrict__ idx_hw,
                                 int* __restrict__ cnt_hw, int* __restrict__ cnt_n) {
    int t = blockIdx.x * blockDim.x + threadIdx.x;
    if (t >= Bz * N0) return;
    int b = t >> 14;
    float2 l = ((const float2*)loc)[t];
    float lx = (fminf(fmaxf(l.x, -1.f), 1.f) + 1.f) * 0.5f;
    float ly = (fminf(fmaxf(l.y, -1.f), 1.f) + 1.f) * 0.5f;
    int xi = (int)rintf(lx * (WW - 1));
    int yi = (int)rintf(ly * (HH - 1));
    int ihw = yi * WW + xi;
    idx_hw[t] = ihw;
    atomicAdd(&cnt_hw[b * HWSZ + ihw], 1);
    atomicAdd(&cnt_n [b * NTOK + idx_agg[t]], 1);
}

// fused scan + fill with value materialization
__global__ __launch_bounds__(1024) void scanfill_kernel(
    const int* __restrict__ cnt_hw, int* __restrict__ off_hw,
    const int* __restrict__ idx_hw, const int* __restrict__ idx_aggs,
    const int* __restrict__ idx_agg,
    int* __restrict__ vhw_src, int* __restrict__ vhw_agg,
    const int* __restrict__ cnt_n, int* __restrict__ off_n,
    const float* __restrict__ aggw,
    int* __restrict__ vn_hw, float* __restrict__ vn_w) {
    __shared__ int sm[1024];
    __shared__ int scur[4096];
    int blk = blockIdx.x, t = threadIdx.x;
    bool is_hw = blk < Bz;
    int b = is_hw ? blk : blk - Bz;
    const int* cnt = is_hw ? cnt_hw : cnt_n;
    int* off = is_hw ? off_hw : off_n;
    const int* c = cnt + b * 4096;
    int v0 = c[t*4], v1 = c[t*4+1], v2 = c[t*4+2], v3 = c[t*4+3];
    int tot = v0 + v1 + v2 + v3;
    sm[t] = tot;
    __syncthreads();
    #pragma unroll
    for (int o = 1; o < 1024; o <<= 1) {
        int u = (t >= o) ? sm[t - o] : 0;
        __syncthreads();
        sm[t] += u;
        __syncthreads();
    }
    int base = sm[t] - tot;
    int* of = off + b * 4096;
    of[t*4]   = base;            scur[t*4]   = base;
    of[t*4+1] = base + v0;       scur[t*4+1] = base + v0;
    of[t*4+2] = base + v0+v1;    scur[t*4+2] = base + v0+v1;
    of[t*4+3] = base + v0+v1+v2; scur[t*4+3] = base + v0+v1+v2;
    __syncthreads();
    if (is_hw) {
        const int* kh = idx_hw  + (size_t)b * N0;
        const int* s1 = idx_aggs + (size_t)b * N0;
        const int* s2 = idx_agg  + (size_t)b * N0;
        int* o1 = vhw_src + (size_t)b * N0;
        int* o2 = vhw_agg + (size_t)b * N0;
        for (int p = t; p < N0; p += 1024) {
            int pos = atomicAdd(&scur[kh[p]], 1);
            o1[pos] = s1[p];
            o2[pos] = s2[p];
        }
    } else {
        const int* kn = idx_agg + (size_t)b * N0;
        const int* s1 = idx_hw  + (size_t)b * N0;
        const float* s2 = aggw  + (size_t)b * N0;
        int* o1 = vn_hw + (size_t)b * N0;
        float* o2 = vn_w + (size_t)b * N0;
        for (int p = t; p < N0; p += 1024) {
            int pos = atomicAdd(&scur[kn[p]], 1);
            o1[pos] = s1[p];
            o2[pos] = s2[p];
        }
    }
}

// ---------------- token2map #1: warp-parallel fused LN, prefetch pipeline,
// writes SR-GEMM A2 directly (fused im2col + bf16 split) + confmap ----------------
__global__ __launch_bounds__(128) void gather_t2m1_kernel(
    const float* __restrict__ xsrc, const float* __restrict__ confs,
    const float* __restrict__ ln_g, const float* __restrict__ ln_b,
    const int* __restrict__ off_hw, const int* __restrict__ cnt_hw,
    const int* __restrict__ vhw_src,
    __nv_bfloat16* __restrict__ a2, float* __restrict__ confmap) {
    __shared__ float4 s_part[4][32];
    __shared__ float  s_conf[4];
    int cell = blockIdx.x;
    int b = cell >> 12;
    int tid = threadIdx.x;
    int warp = tid >> 5, lane = tid & 31;
    int start = off_hw[cell];
    int n = cnt_hw[cell];
    const int* vl = vhw_src + (size_t)b * N0;
    float4 gg = ((const float4*)ln_g)[lane];
    float4 bb = ((const float4*)ln_b)[lane];
    float4 acc = make_float4(0.f, 0.f, 0.f, 0.f);
    float cs = 0.f;
    // software-pipelined: prefetch next point's row while reducing current
    int j = warp;
    float4 v;
    int i_cur = -1;
    if (j < n) {
        i_cur = vl[start + j];
        v = ((const float4*)(xsrc + ((size_t)b * NS + i_cur) * CC))[lane];
    }
    for (; j < n; j += 4) {
        float4 vn;
        int i_next = -1;
        if (j + 4 < n) {
            i_next = vl[start + j + 4];
            vn = ((const float4*)(xsrc + ((size_t)b * NS + i_next) * CC))[lane];
        }
        float s1 = v.x + v.y + v.z + v.w;
        float s2 = v.x*v.x + v.y*v.y + v.z*v.z + v.w*v.w;
        #pragma unroll
        for (int o = 16; o; o >>= 1) {
            s1 += __shfl_xor_sync(0xffffffffu, s1, o);
            s2 += __shfl_xor_sync(0xffffffffu, s2, o);
        }
        float mean = s1 * (1.0f / CC);
        float var  = s2 * (1.0f / CC) - mean * mean;
        float rstd = rsqrtf(var + 1e-5f);
        acc.x += (v.x - mean) * rstd * gg.x + bb.x;
        acc.y += (v.y - mean) * rstd * gg.y + bb.y;
        acc.z += (v.z - mean) * rstd * gg.z + bb.z;
        acc.w += (v.w - mean) * rstd * gg.w + bb.w;
        if (lane == 0) cs += confs[(size_t)b * NS + i_cur];
        v = vn;
        i_cur = i_next;
    }
    s_part[warp][lane] = acc;
    if (lane == 0) s_conf[warp] = cs;
    __syncthreads();
    if (tid < 32) {
        float4 a0 = s_part[0][tid], a1 = s_part[1][tid],
               a2v = s_part[2][tid], a3 = s_part[3][tid];
        float inv = 1.0f / fmaxf((float)n, 1.0f);
        float4 o;
        o.x = (a0.x + a1.x + a2v.x + a3.x) * inv;
        o.y = (a0.y + a1.y + a2v.y + a3.y) * inv;
        o.z = (a0.z + a1.z + a2v.z + a3.z) * inv;
        o.w = (a0.w + a1.w + a2v.w + a3.w) * inv;
        // fused im2col: cell -> (A2 row, column block)
        int yy = (cell >> 6) & 63, xx = cell & 63;
        int prow = b * 256 + (yy >> 2) * 16 + (xx >> 2);
        int colbase = ((yy & 3) * 4 + (xx & 3)) * 128;
        BPack hi, lo;
        split4(o, hi, lo);
        __nv_bfloat16* dst = a2 + (size_t)prow * 4096 + colbase + tid * 4;
        *(uint2*)dst          = hi.u;
        *(uint2*)(dst + 2048) = lo.u;
        if (tid == 0)
            confmap[cell] = (s_conf[0] + s_conf[1] + s_conf[2] + s_conf[3]) * inv;
    }
}

// ---------------- token2map #2 gather (bf16 h, 512ch) -> bf16 hmap, direct list ----------------
__global__ __launch_bounds__(128) void gather_t2m2_kernel(
    const __nv_bfloat16* __restrict__ h,
    const int* __restrict__ off_hw, const int* __restrict__ cnt_hw,
    const int* __restrict__ vhw_agg, __nv_bfloat16* __restrict__ hmap) {
    __shared__ int s_row[128];
    int cell = blockIdx.x;
    int b = cell >> 12;
    int tid = threadIdx.x;
    int start = off_hw[cell];
    int n = cnt_hw[cell];
    const int* vl = vhw_agg + (size_t)b * N0;
    float4 sum = make_float4(0.f, 0.f, 0.f, 0.f);
    for (int base = 0; base < n; base += 128) {
        int m = min(128, n - base);
        if (tid < m) s_row[tid] = vl[start + base + tid];
        __syncthreads();
        for (int j = 0; j < m; j++) {
            const __nv_bfloat162* vp = (const __nv_bfloat162*)(h +
                ((size_t)b * NTOK + s_row[j]) * HID);
            __nv_bfloat162 p0 = vp[tid*2], p1 = vp[tid*2+1];
            float2 f0 = __bfloat1622float2(p0);
            float2 f1 = __bfloat1622float2(p1);
            sum.x += f0.x; sum.y += f0.y; sum.z += f1.x; sum.w += f1.y;
        }
        __syncthreads();
    }
    float inv = 1.0f / fmaxf((float)n, 1.0f);
    BPack o;
    o.h[0] = __float2bfloat16(sum.x * inv);
    o.h[1] = __float2bfloat16(sum.y * inv);
    o.h[2] = __float2bfloat16(sum.z * inv);
    o.h[3] = __float2bfloat16(sum.w * inv);
    *(uint2*)(hmap + (size_t)cell * HID + tid * 4) = o.u;
}

// ---------------- map2token gather + dwskip + gelu + split -> A2, direct lists ----------------
__global__ __launch_bounds__(128) void gather_m2t_kernel(
    const __nv_bfloat16* __restrict__ hmap2,
    const int* __restrict__ off_n, const int* __restrict__ cnt_n,
    const int* __restrict__ vn_hw, const float* __restrict__ vn_w,
    const __nv_bfloat16* __restrict__ h, const float* __restrict__ skip,
    __nv_bfloat16* __restrict__ a2) {
    __shared__ int   s_hw[128];
    __shared__ float s_w [128];
    int tok = blockIdx.x;
    int b = tok >> 12;
    int tid = threadIdx.x;
    int start = off_n[tok];
    int n = cnt_n[tok];
    const int* vl = vn_hw + (size_t)b * N0;
    const float* wl = vn_w + (size_t)b * N0;
    float4 sum = make_float4(0.f, 0.f, 0.f, 0.f);
    float den = 0.f;
    for (int base = 0; base < n; base += 128) {
        int m = min(128, n - base);
        if (tid < m) {
            s_hw[tid] = vl[start + base + tid];
            s_w[tid]  = wl[start + base + tid];
        }
        __syncthreads();
        for (int j = 0; j < m; j++) {
            float w = s_w[j];
            const __nv_bfloat162* vp = (const __nv_bfloat162*)(hmap2 +
                ((size_t)b * HWSZ + s_hw[j]) * HID);
            __nv_bfloat162 p0 = vp[tid*2], p1 = vp[tid*2+1];
            float2 f0 = __bfloat1622float2(p0);
            float2 f1 = __bfloat1622float2(p1);
            sum.x += w * f0.x; sum.y += w * f0.y; sum.z += w * f1.x; sum.w += w * f1.y;
            den += w;
        }
        __syncthreads();
    }
    float inv = 1.0f / fmaxf(den, 1e-6f);
    const __nv_bfloat162* hp = (const __nv_bfloat162*)(h + (size_t)tok * HID);
    __nv_bfloat162 h0 = hp[tid*2], h1 = hp[tid*2+1];
    float2 hf0 = __bfloat1622float2(h0);
    float2 hf1 = __bfloat1622float2(h1);
    float4 sk = ((const float4*)skip)[tid];
    float4 v;
    v.x = sum.x * inv + hf0.x * sk.x;
    v.y = sum.y * inv + hf0.y * sk.y;
    v.z = sum.z * inv + hf1.x * sk.z;
    v.w = sum.w * inv + hf1.y * sk.w;
    v.x = 0.5f * v.x * (1.0f + erff(v.x * 0.70710678118654752f));
    v.y = 0.5f * v.y * (1.0f + erff(v.y * 0.70710678118654752f));
    v.z = 0.5f * v.z * (1.0f + erff(v.z * 0.70710678118654752f));
    v.w = 0.5f * v.w * (1.0f + erff(v.w * 0.70710678118654752f));
    BPack hi, lo;
    split4(v, hi, lo);
    __nv_bfloat16* base2 = a2 + (size_t)tok * 1024;
    *(uint2*)(base2 + tid*4)        = hi.u;
    *(uint2*)(base2 + 512 + tid*4)  = lo.u;
}

__global__ void confp_kernel(const float* __restrict__ conf_map, float* __restrict__ confp) {
    int t = blockIdx.x * blockDim.x + threadIdx.x;
    if (t >= Bz * M2) return;
    int b = t >> 8;
    int p = t & 255;
    int oy = p >> 4, ox = p & 15;
    float s = 0.f;
    #pragma unroll
    for (int i = 0; i < 4; i++)
        #pragma unroll
        for (int j = 0; j < 4; j++)
            s += conf_map[b * HWSZ + (oy * 4 + i) * WW + (ox * 4 + j)];
    confp[t] = s * (1.0f / 16.0f);
}

// W [K][N] f32 -> W2 [2K][N] bf16: rows [whi | wlo]
__global__ void conv3_W_kernel(const float* __restrict__ in, __nv_bfloat16* __restrict__ out,
                               int K, int N) {
    int t = blockIdx.x * blockDim.x + threadIdx.x;
    int nq = N >> 2;
    if (t >= K * nq) return;
    int k = t / nq, n4 = t - k * nq;
    float4 v = ((const float4*)in)[t];
    BPack hi, lo;
    split4(v, hi, lo);
    *(uint2*)(out + (size_t)k*N + n4*4)        = hi.u;
    *(uint2*)(out + (size_t)(K + k)*N + n4*4)  = lo.u;
}

// ---------------- pipelined bf16 HMMA GEMM (3-stage, wrap-indexed 3-term) ----------------
#define AS_STRIDE 56
#define BS_STRIDE 136
#define AS_ELEMS  (128 * AS_STRIDE)
#define BS_ELEMS  (32 * BS_STRIDE)
#define HG_SMEM   (3 * (AS_ELEMS + BS_ELEMS) * 2)
__global__ __launch_bounds__(256, 2) void hgemm_kernel(
    const __nv_bfloat16* __restrict__ A, const __nv_bfloat16* __restrict__ B,
    const float* __restrict__ bias, const float* __restrict__ res,
    float* __restrict__ C, __nv_bfloat16* __restrict__ Cbf,
    int M, int N, int K, int KS) {
    extern __shared__ __align__(16) __nv_bfloat16 smbuf[];
    __nv_bfloat16* As0 = smbuf;
    __nv_bfloat16* Bs0 = smbuf + 3 * AS_ELEMS;
    int bm = blockIdx.y * 128;
    int bn = blockIdx.x * 128;
    int z  = blockIdx.z;
    int tid = threadIdx.x, lane = tid & 31, wid = tid >> 5;
    int wm = (wid >> 2) * 64, wn = (wid & 3) * 32;
    int K2 = 2 * K;

    float c[4][4][4];
    #pragma unroll
    for (int mt = 0; mt < 4; mt++)
        #pragma unroll
        for (int nt = 0; nt < 4; nt++)
            #pragma unroll
            for (int i = 0; i < 4; i++) c[mt][nt][i] = 0.f;

    int arow0 = tid >> 2, ach = tid & 3;
    int NIT = KS / 32;
    int kbase = z * KS;

    auto load_stage = [&](int st, int k0) {
        int ka = (k0 < K2) ? k0 : k0 - K2;
        int kb = (k0 < K)  ? k0 : k0 - K;
        __nv_bfloat16* Asp = As0 + st * AS_ELEMS;
        __nv_bfloat16* Bsp = Bs0 + st * BS_ELEMS;
        #pragma unroll
        for (int i = 0; i < 2; i++) {
            int row = arow0 + i * 64;
            cp16(&Asp[row * AS_STRIDE + ach * 8],
                 &A[(size_t)(bm + row) * K2 + ka + ach * 8]);
        }
        #pragma unroll
        for (int j = 0; j < 2; j++) {
            int idx = tid + j * 256;
            int row = idx >> 4, ch = idx & 15;
            cp16(&Bsp[row * BS_STRIDE + ch * 8],
                 &B[(size_t)(kb + row) * N + bn + ch * 8]);
        }
    };

    load_stage(0, kbase);
    CP_COMMIT();
    load_stage(1, kbase + 32);
    CP_COMMIT();

    for (int it = 0; it < NIT; it++) {
        CP_WAIT(1);
        __syncthreads();
        int st = it % 3;
        const __nv_bfloat16* Asp = As0 + st * AS_ELEMS;
        const __nv_bfloat16* Bsp = Bs0 + st * BS_ELEMS;
        #pragma unroll
        for (int ks = 0; ks < 2; ks++) {
            uint32_t a[4][4];
            #pragma unroll
            for (int mt = 0; mt < 4; mt++) {
                const void* p = &Asp[(wm + mt*16 + (lane & 15)) * AS_STRIDE + ks*16 + (lane >> 4) * 8];
                ldsm4(a[mt][0], a[mt][1], a[mt][2], a[mt][3], p);
            }
            uint32_t bfr[4][2];
            #pragma unroll
            for (int np = 0; np < 2; np++) {
                int g = lane >> 3, r = lane & 7;
                const void* p = &Bsp[(ks*16 + (g & 1)*8 + r) * BS_STRIDE + wn + np*16 + (g >> 1) * 8];
                uint32_t r0, r1, r2, r3;
                ldsm4t(r0, r1, r2, r3, p);
                bfr[np*2][0] = r0;   bfr[np*2][1] = r1;
                bfr[np*2+1][0] = r2; bfr[np*2+1][1] = r3;
            }
            #pragma unroll
            for (int mt = 0; mt < 4; mt++)
                #pragma unroll
                for (int nt = 0; nt < 4; nt++)
                    mma16816(c[mt][nt], a[mt], bfr[nt]);
        }
        __syncthreads();
        if (it + 2 < NIT) load_stage((it + 2) % 3, kbase + (it + 2) * 32);
        CP_COMMIT();
    }

    int r0 = lane >> 2, cc = (lane & 3) * 2;
    float* Cz = C ? (C + (size_t)z * M * N) : nullptr;
    #pragma unroll
    for (int mt = 0; mt < 4; mt++) {
        #pragma unroll
        for (int nt = 0; nt < 4; nt++) {
            int row = bm + wm + mt*16 + r0;
            int col = bn + wn + nt*8 + cc;
            float2 v0 = make_float2(c[mt][nt][0], c[mt][nt][1]);
            float2 v1 = make_float2(c[mt][nt][2], c[mt][nt][3]);
            if (bias) {
                float b0 = bias[col], b1 = bias[col+1];
                v0.x += b0; v0.y += b1; v1.x += b0; v1.y += b1;
            }
            size_t off0 = (size_t)row * N + col;
            size_t off1 = (size_t)(row + 8) * N + col;
            if (Cbf) {
                __nv_bfloat162 o0 = __floats2bfloat162_rn(v0.x, v0.y);
                __nv_bfloat162 o1 = __floats2bfloat162_rn(v1.x, v1.y);
                *(__nv_bfloat162*)(Cbf + off0) = o0;
                *(__nv_bfloat162*)(Cbf + off1) = o1;
            } else {
                if (res) {
                    float2 rr0 = *(const float2*)(res + off0);
                    float2 rr1 = *(const float2*)(res + off1);
                    v0.x += rr0.x; v0.y += rr0.y; v1.x += rr1.x; v1.y += rr1.y;
                }
                *(float2*)(Cz + off0) = v0;
                *(float2*)(Cz + off1) = v1;
            }
        }
    }
}

// ---------------- fused attention: unshifted softmax + f32x2, bf16 q, 256 thr ----------------
__global__ __launch_bounds__(256) void attn_kernel(
    const __nv_bfloat16* __restrict__ q, const float* __restrict__ kv,
    const float* __restrict__ confp, __nv_bfloat16* __restrict__ a2) {
    extern __shared__ float sm[];
    float* ks = sm;
    float* vs = sm + M2 * DH;
    float* cp = sm + 2 * M2 * DH;
    int bh = blockIdx.y;
    int b = bh >> 1, h = bh & 1;
    int tid = threadIdx.x;
    for (int t = tid; t < M2 * 16; t += 256) {
        int m = t >> 4, j4 = t & 15;
        const float* row = kv + ((size_t)(b * M2 + m)) * 256;
        ((float4*)ks)[m * 16 + j4] = ((const float4*)(row + h * DH))[j4];
        ((float4*)vs)[m * 16 + j4] = ((const float4*)(row + 128 + h * DH))[j4];
    }
    for (int t = tid; t < M2; t += 256) cp[t] = confp[b * M2 + t];
    __syncthreads();

    int n = blockIdx.x * 256 + tid;
    const __nv_bfloat162* qp = (const __nv_bfloat162*)(q + ((size_t)(b * NTOK + n)) * CC + h * DH);
    u64t q2[32];
    #pragma unroll
    for (int t = 0; t < 32; t++) {
        float2 f = __bfloat1622float2(qp[t]);
        q2[t] = pack2f(f.x * 0.125f, f.y * 0.125f);
    }
    u64t acc2[32];
    #pragma unroll
    for (int j = 0; j < 32; j++) acc2[j] = 0ULL;
    float l = 0.f;

    for (int m = 0; m < M2; m++) {
        const ulonglong2* kp = (const ulonglong2*)(ks + m * DH);
        u64t s0 = 0ULL, s1 = 0ULL, s2 = 0ULL, s3 = 0ULL;
        #pragma unroll
        for (int t = 0; t < 16; t += 2) {
            ulonglong2 k0 = kp[t];
            ulonglong2 k1 = kp[t+1];
            s0 = fma2(q2[2*t],   k0.x, s0);
            s1 = fma2(q2[2*t+1], k0.y, s1);
            s2 = fma2(q2[2*t+2], k1.x, s2);
            s3 = fma2(q2[2*t+3], k1.y, s3);
        }
        u64t st = add2(add2(s0, s1), add2(s2, s3));
        float slo, shi;
        unpack2(st, slo, shi);
        float p = __expf(slo + shi + cp[m]);
        l += p;
        u64t p2 = dup2(p);
        const ulonglong2* vp = (const ulonglong2*)(vs + m * DH);
        #pragma unroll
        for (int t = 0; t < 16; t++) {
            ulonglong2 vv = vp[t];
            acc2[2*t]   = fma2(p2, vv.x, acc2[2*t]);
            acc2[2*t+1] = fma2(p2, vv.y, acc2[2*t+1]);
        }
    }
    float inv = 1.0f / l;
    __nv_bfloat16* a2row = a2 + (size_t)(b * NTOK + n) * 256 + h * DH;
    #pragma unroll
    for (int t = 0; t < 16; t++) {
        float c0, c1, c2, c3;
        unpack2(acc2[2*t], c0, c1);
        unpack2(acc2[2*t+1], c2, c3);
        float4 o4 = make_float4(c0 * inv, c1 * inv, c2 * inv, c3 * inv);
        BPack hi, lo;
        split4(o4, hi, lo);
        *(uint2*)(a2row + t*4)        = hi.u;
        *(uint2*)(a2row + 128 + t*4)  = lo.u;
    }
}

// depthwise 3x3 SAME conv over (B,64,64,512), bf16 in / bf16 out
__global__ void dwconv_kernel(const __nv_bfloat16* __restrict__ hmap, const float* __restrict__ w,
                              const float* __restrict__ bias, __nv_bfloat16* __restrict__ out) {
    __shared__ float ws[9 * HID];
    __shared__ float bs[HID];
    int b = blockIdx.y, y = blockIdx.x;
    for (int t = threadIdx.x; t < 9 * HID; t += blockDim.x) ws[t] = w[t];
    for (int t = threadIdx.x; t < HID; t += blockDim.x) bs[t] = bias[t];
    __syncthreads();
    const __nv_bfloat16* base = hmap + ((size_t)b * HWSZ) * HID;
    __nv_bfloat16* ob = out + ((size_t)(b * HWSZ) + y * WW) * HID;
    const int H2 = HID / 2;
    for (int t = threadIdx.x; t < WW * H2; t += blockDim.x) {
        int x = t / H2;
        int c2 = t - x * H2;
        int c = c2 * 2;
        float accx = bs[c], accy = bs[c + 1];
        #pragma unroll
        for (int dy = -1; dy <= 1; dy++) {
            int yy = y + dy;
            if ((unsigned)yy >= HH) continue;
            #pragma unroll
            for (int dx = -1; dx <= 1; dx++) {
                int xx = x + dx;
                if ((unsigned)xx >= WW) continue;
                __nv_bfloat162 p = *(const __nv_bfloat162*)(base +
                    ((size_t)(yy * WW + xx)) * HID + c);
                float2 f = __bfloat1622float2(p);
                int wi = ((dy+1)*3 + dx+1) * HID + c;
                accx += f.x * ws[wi];
                accy += f.y * ws[wi + 1];
            }
        }
        *(__nv_bfloat162*)(ob + (size_t)x * HID + c) = __floats2bfloat162_rn(accx, accy);
    }
}

// ---------------- host helpers ----------------
static __nv_bfloat16 *s_a3, *s_w3;

static void hgemm_run(const float* W, const float* bias, const float* res,
                      float* C, __nv_bfloat16* Cbf, int M, int Nc, int K) {
    conv3_W_kernel<<<(K * Nc / 4 + 255) / 256, 256>>>(W, s_w3, K, Nc);
    cudaFuncSetAttribute(hgemm_kernel, cudaFuncAttributeMaxDynamicSharedMemorySize, HG_SMEM);
    dim3 grid(Nc / 128, M / 128, 1);
    hgemm_kernel<<<grid, 256, HG_SMEM>>>(s_a3, s_w3, bias, res, C, Cbf, M, Nc, K, 3 * K);
}

extern "C" void kernel_launch(void* const* d_in, const int* in_sizes, int n_in,
                              void* d_out, int out_size) {
    const float* x        = (const float*)d_in[0];
    const float* loc      = (const float*)d_in[1];
    const int*   idx_agg  = (const int*)  d_in[2];
    const float* aggw     = (const float*)d_in[3];
    const float* xsrc     = (const float*)d_in[4];
    const int*   idx_aggs = (const int*)  d_in[5];
    const float* confs    = (const float*)d_in[6];
    const float* ln1_g    = (const float*)d_in[7];
    const float* ln1_b    = (const float*)d_in[8];
    const float* ln2_g    = (const float*)d_in[9];
    const float* ln2_b    = (const float*)d_in[10];
    const float* wq       = (const float*)d_in[11];
    const float* wkv      = (const float*)d_in[12];
    const float* wproj    = (const float*)d_in[13];
    const float* bproj    = (const float*)d_in[14];
    const float* sr_w     = (const float*)d_in[15];
    const float* sr_b     = (const float*)d_in[16];
    const float* srn_g    = (const float*)d_in[17];
    const float* srn_b    = (const float*)d_in[18];
    const float* fc1_w    = (const float*)d_in[19];
    const float* fc1_b    = (const float*)d_in[20];
    const float* dw_w     = (const float*)d_in[21];
    const float* dw_b     = (const float*)d_in[22];
    const float* dwskip   = (const float*)d_in[23];
    const float* fc2_w    = (const float*)d_in[24];
    const float* fc2_b    = (const float*)d_in[25];
    float* out = (float*)d_out;

    float *p_confmap, *p_psum, *p_confp, *p_kv, *p_x1, *p_vn_w;
    __nv_bfloat16 *p_q, *p_h, *p_hmap, *p_hmap2;
    int *p_idx_hw, *p_cnt_hw, *p_off_hw, *p_cnt_n, *p_off_n,
        *p_vhw_src, *p_vhw_agg, *p_vn_hw;
    cudaGetSymbolAddress((void**)&p_q, g_q);
    cudaGetSymbolAddress((void**)&p_idx_hw, g_idx_hw);
    cudaGetSymbolAddress((void**)&p_cnt_hw, g_cnt_hw);
    cudaGetSymbolAddress((void**)&p_off_hw, g_off_hw);
    cudaGetSymbolAddress((void**)&p_cnt_n, g_cnt_n);
    cudaGetSymbolAddress((void**)&p_off_n, g_off_n);
    cudaGetSymbolAddress((void**)&p_vhw_src, g_vhw_src);
    cudaGetSymbolAddress((void**)&p_vhw_agg, g_vhw_agg);
    cudaGetSymbolAddress((void**)&p_vn_hw, g_vn_hw);
    cudaGetSymbolAddress((void**)&p_vn_w, g_vn_w);
    cudaGetSymbolAddress((void**)&p_confmap, g_confmap);
    cudaGetSymbolAddress((void**)&p_psum, g_psum);
    cudaGetSymbolAddress((void**)&p_confp, g_confp);
    cudaGetSymbolAddress((void**)&p_kv, g_kv);
    cudaGetSymbolAddress((void**)&p_x1, g_x1);
    cudaGetSymbolAddress((void**)&p_h, g_h);
    cudaGetSymbolAddress((void**)&p_hmap, g_hmap);
    cudaGetSymbolAddress((void**)&p_hmap2, g_hmap2);
    cudaGetSymbolAddress((void**)&s_a3, g_a3);
    cudaGetSymbolAddress((void**)&s_w3, g_w3);

    // 1. CSR build
    zero2_kernel<<<32, 256>>>(p_cnt_hw, p_cnt_n, Bz*HWSZ/4);
    gridcount_kernel<<<(Bz*N0 + 255) / 256, 256>>>(loc, idx_agg, p_idx_hw, p_cnt_hw, p_cnt_n);
    scanfill_kernel<<<16, 1024>>>(p_cnt_hw, p_off_hw, p_idx_hw, idx_aggs, idx_agg,
                                  p_vhw_src, p_vhw_agg,
                                  p_cnt_n, p_off_n, aggw, p_vn_hw, p_vn_w);

    // 2. token2map #1: fused LN + fused im2col + bf16 split -> SR GEMM A2
    gather_t2m1_kernel<<<Bz*HWSZ, 128>>>(xsrc, confs, ln1_g, ln1_b,
                                         p_off_hw, p_cnt_hw, p_vhw_src,
                                         s_a3, p_confmap);

    // 3. SR conv: split-K HMMA directly on A2
    conv3_W_kernel<<<(2048*128/4 + 255) / 256, 256>>>(sr_w, s_w3, 2048, 128);
    {
        cudaFuncSetAttribute(hgemm_kernel, cudaFuncAttributeMaxDynamicSharedMemorySize, HG_SMEM);
        dim3 grid(1, 16, KSP);
        hgemm_kernel<<<grid, 256, HG_SMEM>>>(s_a3, s_w3, nullptr, nullptr, p_psum, nullptr,
                                             2048, 128, 2048, 6144 / KSP);
    }

    // 4. conf pooling
    confp_kernel<<<(Bz*M2 + 255) / 256, 256>>>(p_confmap, p_confp);

    // 5a. reduce+LN(srn)+split -> a2; wkv GEMM
    skred_ln_split_kernel<<<(2048 + 7) / 8, 256>>>(p_psum, sr_b, srn_g, srn_b, s_a3);
    hgemm_run(wkv, nullptr, nullptr, p_kv, nullptr, 2048, 256, 128);

    // 5b. LN(ln1,x)+split -> a2; wq GEMM (bf16 q out)
    ln_split_kernel<<<(Bz*NTOK + 7) / 8, 256>>>(x, ln1_g, ln1_b, s_a3, Bz*NTOK);
    hgemm_run(wq, nullptr, nullptr, nullptr, p_q, Bz*NTOK, 128, 128);

    // 6. fused attention
    {
        size_t smem = (2 * M2 * DH + M2) * sizeof(float);
        cudaFuncSetAttribute(attn_kernel, cudaFuncAttributeMaxDynamicSharedMemorySize, (int)smem);
        dim3 grid(NTOK / 256, Bz * NHEADS);
        attn_kernel<<<grid, 256, smem>>>(p_q, p_kv, p_confp, s_a3);
    }

    // 7. output projection + residual
    hgemm_run(wproj, bproj, x, p_x1, nullptr, Bz*NTOK, 128, 128);

    // 8. ln2+split + fc1 (bf16 h out)
    ln_split_kernel<<<(Bz*NTOK + 7) / 8, 256>>>(p_x1, ln2_g, ln2_b, s_a3, Bz*NTOK);
    hgemm_run(fc1_w, fc1_b, nullptr, nullptr, p_h, Bz*NTOK, 512, 128);

    // 9. token2map #2
    gather_t2m2_kernel<<<Bz*HWSZ, 128>>>(p_h, p_off_hw, p_cnt_hw, p_vhw_agg, p_hmap);

    // 10. depthwise 3x3 SAME conv
    {
        dim3 grid(HH, Bz);
        dwconv_kernel<<<grid, 256>>>(p_hmap, dw_w, dw_b, p_hmap2);
    }

    // 11. map2token + dwskip + gelu + split -> a2
    gather_m2t_kernel<<<Bz*NTOK, 128>>>(p_hmap2, p_off_n, p_cnt_n, p_vn_hw, p_vn_w,
                                        p_h, dwskip, s_a3);

    // 12. fc2 + residual -> output
    hgemm_run(fc2_w, fc2_b, p_x1, out, nullptr, Bz*NTOK, 128, 512);
}

// round 16
// speedup vs baseline: 1.0285x; 1.0047x over previous
#include <cuda_runtime.h>
#include <cuda_bf16.h>
#include <cstdint>
#include <math.h>

// ---------------- problem constants (fixed shapes) ----------------
#define Bz      8
#define NTOK    4096
#define N0      16384
#define NS      16384
#define CC      128
#define HH      64
#define WW      64
#define HWSZ    4096
#define NHEADS  2
#define DH      64
#define M2      256
#define HID     512
#define KSP     8        // split-K factor for SR conv GEMM

// ---------------- packed fp32x2 helpers (attention) ----------------
typedef unsigned long long u64t;
__device__ __forceinline__ u64t dup2(float a) {
    u64t r; asm("mov.b64 %0, {%1, %1};" : "=l"(r) : "f"(a)); return r;
}
__device__ __forceinline__ u64t pack2f(float lo, float hi) {
    u64t r; asm("mov.b64 %0, {%1, %2};" : "=l"(r) : "f"(lo), "f"(hi)); return r;
}
__device__ __forceinline__ void unpack2(u64t v, float& lo, float& hi) {
    asm("mov.b64 {%0, %1}, %2;" : "=f"(lo), "=f"(hi) : "l"(v));
}
__device__ __forceinline__ u64t fma2(u64t a, u64t b, u64t c) {
    u64t d; asm("fma.rn.f32x2 %0, %1, %2, %3;" : "=l"(d) : "l"(a), "l"(b), "l"(c)); return d;
}
__device__ __forceinline__ u64t mul2(u64t a, u64t b) {
    u64t d; asm("mul.rn.f32x2 %0, %1, %2;" : "=l"(d) : "l"(a), "l"(b)); return d;
}
__device__ __forceinline__ u64t add2(u64t a, u64t b) {
    u64t d; asm("add.rn.f32x2 %0, %1, %2;" : "=l"(d) : "l"(a), "l"(b)); return d;
}

// ---------------- mma / ldmatrix / cp.async helpers ----------------
__device__ __forceinline__ void ldsm4(uint32_t& r0, uint32_t& r1, uint32_t& r2, uint32_t& r3,
                                      const void* p) {
    unsigned addr = (unsigned)__cvta_generic_to_shared(p);
    asm volatile("ldmatrix.sync.aligned.m8n8.x4.shared.b16 {%0,%1,%2,%3}, [%4];"
                 : "=r"(r0), "=r"(r1), "=r"(r2), "=r"(r3) : "r"(addr) : "memory");
}
__device__ __forceinline__ void ldsm4t(uint32_t& r0, uint32_t& r1, uint32_t& r2, uint32_t& r3,
                                       const void* p) {
    unsigned addr = (unsigned)__cvta_generic_to_shared(p);
    asm volatile("ldmatrix.sync.aligned.m8n8.x4.trans.shared.b16 {%0,%1,%2,%3}, [%4];"
                 : "=r"(r0), "=r"(r1), "=r"(r2), "=r"(r3) : "r"(addr) : "memory");
}
__device__ __forceinline__ void mma16816(float c[4], const uint32_t a[4], const uint32_t b[2]) {
    asm volatile(
        "mma.sync.aligned.m16n8k16.row.col.f32.bf16.bf16.f32 "
        "{%0,%1,%2,%3}, {%4,%5,%6,%7}, {%8,%9}, {%0,%1,%2,%3};"
        : "+f"(c[0]), "+f"(c[1]), "+f"(c[2]), "+f"(c[3])
        : "r"(a[0]), "r"(a[1]), "r"(a[2]), "r"(a[3]), "r"(b[0]), "r"(b[1]));
}
__device__ __forceinline__ void cp16(void* smem, const void* gmem) {
    unsigned s = (unsigned)__cvta_generic_to_shared(smem);
    asm volatile("cp.async.cg.shared.global [%0], [%1], 16;" :: "r"(s), "l"(gmem) : "memory");
}
#define CP_COMMIT() asm volatile("cp.async.commit_group;" ::: "memory")
#define CP_WAIT(n)  asm volatile("cp.async.wait_group %0;" :: "n"(n) : "memory")

// ---------------- scratch (device globals; no allocation) ----------------
__device__ __align__(16) __nv_bfloat16 g_q [Bz*NTOK*CC];   // bf16 q
__device__ int   g_idx_hw [Bz*N0];

__device__ int   g_cnt_hw [Bz*HWSZ];
__device__ int   g_off_hw [Bz*HWSZ];
__device__ int   g_cnt_n  [Bz*NTOK];
__device__ int   g_off_n  [Bz*NTOK];
// value lists (CSR-ordered consumer data)
__device__ int   g_vhw_src[Bz*N0];
__device__ int   g_vhw_agg[Bz*N0];
__device__ int   g_vn_hw  [Bz*N0];
__device__ float g_vn_w   [Bz*N0];

__device__ float g_confmap[Bz*HWSZ];
__device__ float g_psum   [KSP*2048*CC];
__device__ float g_confp  [2048];
__device__ float g_kv     [2048*256];
__device__ float g_x1     [Bz*NTOK*CC];
__device__ __align__(16) __nv_bfloat16 g_h     [Bz*NTOK*HID];
__device__ __align__(16) __nv_bfloat16 g_hmap  [Bz*HWSZ*HID];
__device__ __align__(16) __nv_bfloat16 g_hmap2 [Bz*HWSZ*HID];

// bf16 split buffers: A2 max = 32768 x 1024 (fc2); W2 max = 4096 x 256
__device__ __align__(16) __nv_bfloat16 g_a3 [(size_t)32768*1024];
__device__ __align__(16) __nv_bfloat16 g_w3 [(size_t)4096*256];

// ---------------- utility ----------------
__global__ void zero2_kernel(int* __restrict__ p1, int* __restrict__ p2, int n4) {
    int i = blockIdx.x * blockDim.x + threadIdx.x;
    int stride = gridDim.x * blockDim.x;
    int4 z = make_int4(0, 0, 0, 0);
    for (; i < n4; i += stride) { ((int4*)p1)[i] = z; ((int4*)p2)[i] = z; }
}

// ---------------- f32 -> bf16 split helpers ----------------
union BPack { __nv_bfloat16 h[4]; uint2 u; };
__device__ __forceinline__ void split4(float4 v, BPack& hi, BPack& lo) {
    hi.h[0] = __float2bfloat16(v.x); lo.h[0] = __float2bfloat16(v.x - __bfloat162float(hi.h[0]));
    hi.h[1] = __float2bfloat16(v.y); lo.h[1] = __float2bfloat16(v.y - __bfloat162float(hi.h[1]));
    hi.h[2] = __float2bfloat16(v.z); lo.h[2] = __float2bfloat16(v.z - __bfloat162float(hi.h[2]));
    hi.h[3] = __float2bfloat16(v.w); lo.h[3] = __float2bfloat16(v.w - __bfloat162float(hi.h[3]));
}

// LayerNorm fused with 2-segment bf16 split: A2 row = [hi(128) | lo(128)]
__global__ void ln_split_kernel(const float* __restrict__ in, const float* __restrict__ g,
                                const float* __restrict__ b, __nv_bfloat16* __restrict__ a2,
                                int rows) {
    int row  = blockIdx.x * 8 + (threadIdx.x >> 5);
    int lane = threadIdx.x & 31;
    if (row >= rows) return;
    float4 v = ((const float4*)(in + (size_t)row * CC))[lane];
    float s = v.x + v.y + v.z + v.w;
    #pragma unroll
    for (int o = 16; o; o >>= 1) s += __shfl_xor_sync(0xffffffffu, s, o);
    float mean = s * (1.0f / CC);
    float dx = v.x - mean, dy = v.y - mean, dz = v.z - mean, dw = v.w - mean;
    float s2 = dx*dx + dy*dy + dz*dz + dw*dw;
    #pragma unroll
    for (int o = 16; o; o >>= 1) s2 += __shfl_xor_sync(0xffffffffu, s2, o);
    float rstd = rsqrtf(s2 * (1.0f / CC) + 1e-5f);
    float4 gg = ((const float4*)g)[lane];
    float4 bb = ((const float4*)b)[lane];
    float4 o4 = make_float4(dx*rstd*gg.x + bb.x, dy*rstd*gg.y + bb.y,
                            dz*rstd*gg.z + bb.z, dw*rstd*gg.w + bb.w);
    BPack hi, lo;
    split4(o4, hi, lo);
    __nv_bfloat16* base = a2 + (size_t)row * 256;
    *(uint2*)(base + lane*4)        = hi.u;
    *(uint2*)(base + 128 + lane*4)  = lo.u;
}

// split-K reduce + bias + LN(srn) + split (SR conv epilogue)
__global__ void skred_ln_split_kernel(const float* __restrict__ part,
                                      const float* __restrict__ bias,
                                      const float* __restrict__ g, const float* __restrict__ b,
                                      __nv_bfloat16* __restrict__ a2) {
    int row  = blockIdx.x * 8 + (threadIdx.x >> 5);
    int lane = threadIdx.x & 31;
    if (row >= 2048) return;
    const int MN = 2048 * CC;
    float4 v = make_float4(0.f, 0.f, 0.f, 0.f);
    #pragma unroll
    for (int zz = 0; zz < KSP; zz++) {
        float4 p = ((const float4*)(part + (size_t)zz * MN + (size_t)row * CC))[lane];
        v.x += p.x; v.y += p.y; v.z += p.z; v.w += p.w;
    }
    float4 bi = ((const float4*)bias)[lane];
    v.x += bi.x; v.y += bi.y; v.z += bi.z; v.w += bi.w;
    float s = v.x + v.y + v.z + v.w;
    #pragma unroll
    for (int o = 16; o; o >>= 1) s += __shfl_xor_sync(0xffffffffu, s, o);
    float mean = s * (1.0f / CC);
    float dx = v.x - mean, dy = v.y - mean, dz = v.z - mean, dw = v.w - mean;
    float s2 = dx*dx + dy*dy + dz*dz + dw*dw;
    #pragma unroll
    for (int o = 16; o; o >>= 1) s2 += __shfl_xor_sync(0xffffffffu, s2, o);
    float rstd = rsqrtf(s2 * (1.0f / CC) + 1e-5f);
    float4 gg = ((const float4*)g)[lane];
    float4 bb = ((const float4*)b)[lane];
    float4 o4 = make_float4(dx*rstd*gg.x + bb.x, dy*rstd*gg.y + bb.y,
                            dz*rstd*gg.z + bb.z, dw*rstd*gg.w + bb.w);
    BPack hi, lo;
    split4(o4, hi, lo);
    __nv_bfloat16* base = a2 + (size_t)row * 256;
    *(uint2*)(base + lane*4)        = hi.u;
    *(uint2*)(base + 128 + lane*4)  = lo.u;
}

// ---------------- CSR build ----------------
__global__ void gridcount_kernel(const float* __restrict__ loc, const int* __restrict__ idx_agg,
                                 int* __restrict__ idx_hw,
                                 int* __restrict__ cnt_hw, int* __restrict__ cnt_n) {
    int t = blockIdx.x * blockDim.x + threadIdx.x;
    if (t >= Bz * N0) return;
    int b = t >> 14;
    float2 l = ((const float2*)loc)[t];
    float lx = (fminf(fmaxf(l.x, -1.f), 1.f) + 1.f) * 0.5f;
    float ly = (fminf(fmaxf(l.y, -1.f), 1.f) + 1.f) * 0.5f;
    int xi = (int)rintf(lx * (WW - 1));
    int yi = (int)rintf(ly * (HH - 1));
    int ihw = yi * WW + xi;
    idx_hw[t] = ihw;
    atomicAdd(&cnt_hw[b * HWSZ + ihw], 1);
    atomicAdd(&cnt_n [b * NTOK + idx_agg[t]], 1);
}

__global__ __launch_bounds__(1024) void scanfill_kernel(
    const int* __restrict__ cnt_hw, int* __restrict__ off_hw,
    const int* __restrict__ idx_hw, const int* __restrict__ idx_aggs,
    const int* __restrict__ idx_agg,
    int* __restrict__ vhw_src, int* __restrict__ vhw_agg,
    const int* __restrict__ cnt_n, int* __restrict__ off_n,
    const float* __restrict__ aggw,
    int* __restrict__ vn_hw, float* __restrict__ vn_w) {
    __shared__ int sm[1024];
    __shared__ int scur[4096];
    int blk = blockIdx.x, t = threadIdx.x;
    bool is_hw = blk < Bz;
    int b = is_hw ? blk : blk - Bz;
    const int* cnt = is_hw ? cnt_hw : cnt_n;
    int* off = is_hw ? off_hw : off_n;
    const int* c = cnt + b * 4096;
    int v0 = c[t*4], v1 = c[t*4+1], v2 = c[t*4+2], v3 = c[t*4+3];
    int tot = v0 + v1 + v2 + v3;
    sm[t] = tot;
    __syncthreads();
    #pragma unroll
    for (int o = 1; o < 1024; o <<= 1) {
        int u = (t >= o) ? sm[t - o] : 0;
        __syncthreads();
        sm[t] += u;
        __syncthreads();
    }
    int base = sm[t] - tot;
    int* of = off + b * 4096;
    of[t*4]   = base;            scur[t*4]   = base;
    of[t*4+1] = base + v0;       scur[t*4+1] = base + v0;
    of[t*4+2] = base + v0+v1;    scur[t*4+2] = base + v0+v1;
    of[t*4+3] = base + v0+v1+v2; scur[t*4+3] = base + v0+v1+v2;
    __syncthreads();
    if (is_hw) {
        const int* kh = idx_hw  + (size_t)b * N0;
        const int* s1 = idx_aggs + (size_t)b * N0;
        const int* s2 = idx_agg  + (size_t)b * N0;
        int* o1 = vhw_src + (size_t)b * N0;
        int* o2 = vhw_agg + (size_t)b * N0;
        for (int p = t; p < N0; p += 1024) {
            int pos = atomicAdd(&scur[kh[p]], 1);
            o1[pos] = s1[p];
            o2[pos] = s2[p];
        }
    } else {
        const int* kn = idx_agg + (size_t)b * N0;
        const int* s1 = idx_hw  + (size_t)b * N0;
        const float* s2 = aggw  + (size_t)b * N0;
        int* o1 = vn_hw + (size_t)b * N0;
        float* o2 = vn_w + (size_t)b * N0;
        for (int p = t; p < N0; p += 1024) {
            int pos = atomicAdd(&scur[kn[p]], 1);
            o1[pos] = s1[p];
            o2[pos] = s2[p];
        }
    }
}

// ---------------- token2map #1: WARP-PER-CELL, fused LN + im2col + split ----------------
// 256-thread blocks; warp w handles cell = blk*8 + w. No barriers, no smem.
__global__ __launch_bounds__(256) void gather_t2m1_kernel(
    const float* __restrict__ xsrc, const float* __restrict__ confs,
    const float* __restrict__ ln_g, const float* __restrict__ ln_b,
    const int* __restrict__ off_hw, const int* __restrict__ cnt_hw,
    const int* __restrict__ vhw_src,
    __nv_bfloat16* __restrict__ a2, float* __restrict__ confmap) {
    int warp = threadIdx.x >> 5, lane = threadIdx.x & 31;
    int cell = blockIdx.x * 8 + warp;
    int b = cell >> 12;
    int start = off_hw[cell];
    int n = cnt_hw[cell];
    const int* vl = vhw_src + (size_t)b * N0;
    float4 gg = ((const float4*)ln_g)[lane];
    float4 bb = ((const float4*)ln_b)[lane];
    float4 acc = make_float4(0.f, 0.f, 0.f, 0.f);
    float cs = 0.f;
    // software pipeline depth 1 over the cell's points
    float4 v;
    int i_cur = -1;
    if (n > 0) {
        i_cur = vl[start];
        v = ((const float4*)(xsrc + ((size_t)b * NS + i_cur) * CC))[lane];
    }
    for (int j = 0; j < n; j++) {
        float4 vn;
        int i_next = -1;
        if (j + 1 < n) {
            i_next = vl[start + j + 1];
            vn = ((const float4*)(xsrc + ((size_t)b * NS + i_next) * CC))[lane];
        }
        float s1 = v.x + v.y + v.z + v.w;
        float s2 = v.x*v.x + v.y*v.y + v.z*v.z + v.w*v.w;
        #pragma unroll
        for (int o = 16; o; o >>= 1) {
            s1 += __shfl_xor_sync(0xffffffffu, s1, o);
            s2 += __shfl_xor_sync(0xffffffffu, s2, o);
        }
        float mean = s1 * (1.0f / CC);
        float var  = s2 * (1.0f / CC) - mean * mean;
        float rstd = rsqrtf(var + 1e-5f);
        acc.x += (v.x - mean) * rstd * gg.x + bb.x;
        acc.y += (v.y - mean) * rstd * gg.y + bb.y;
        acc.z += (v.z - mean) * rstd * gg.z + bb.z;
        acc.w += (v.w - mean) * rstd * gg.w + bb.w;
        if (lane == 0) cs += confs[(size_t)b * NS + i_cur];
        v = vn;
        i_cur = i_next;
    }
    float inv = 1.0f / fmaxf((float)n, 1.0f);
    float4 o = make_float4(acc.x * inv, acc.y * inv, acc.z * inv, acc.w * inv);
    // fused im2col: cell -> (A2 row, column block)
    int yy = (cell >> 6) & 63, xx = cell & 63;
    int prow = b * 256 + (yy >> 2) * 16 + (xx >> 2);
    int colbase = ((yy & 3) * 4 + (xx & 3)) * 128;
    BPack hi, lo;
    split4(o, hi, lo);
    __nv_bfloat16* dst = a2 + (size_t)prow * 4096 + colbase + lane * 4;
    *(uint2*)dst          = hi.u;
    *(uint2*)(dst + 2048) = lo.u;
    if (lane == 0) confmap[cell] = cs * inv;
}

// ---------------- token2map #2 gather (bf16 h, 512ch) -> bf16 hmap, prefetch ----------------
__global__ __launch_bounds__(128) void gather_t2m2_kernel(
    const __nv_bfloat16* __restrict__ h,
    const int* __restrict__ off_hw, const int* __restrict__ cnt_hw,
    const int* __restrict__ vhw_agg, __nv_bfloat16* __restrict__ hmap) {
    __shared__ int s_row[128];
    int cell = blockIdx.x;
    int b = cell >> 12;
    int tid = threadIdx.x;
    int start = off_hw[cell];
    int n = cnt_hw[cell];
    const int* vl = vhw_agg + (size_t)b * N0;
    float4 sum = make_float4(0.f, 0.f, 0.f, 0.f);
    for (int base = 0; base < n; base += 128) {
        int m = min(128, n - base);
        if (tid < m) s_row[tid] = vl[start + base + tid];
        __syncthreads();
        __nv_bfloat162 c0, c1;
        {
            const __nv_bfloat162* vp = (const __nv_bfloat162*)(h +
                ((size_t)b * NTOK + s_row[0]) * HID);
            c0 = vp[tid*2]; c1 = vp[tid*2+1];
        }
        for (int j = 0; j < m; j++) {
            __nv_bfloat162 n0, n1;
            if (j + 1 < m) {
                const __nv_bfloat162* vp = (const __nv_bfloat162*)(h +
                    ((size_t)b * NTOK + s_row[j+1]) * HID);
                n0 = vp[tid*2]; n1 = vp[tid*2+1];
            }
            float2 f0 = __bfloat1622float2(c0);
            float2 f1 = __bfloat1622float2(c1);
            sum.x += f0.x; sum.y += f0.y; sum.z += f1.x; sum.w += f1.y;
            c0 = n0; c1 = n1;
        }
        __syncthreads();
    }
    float inv = 1.0f / fmaxf((float)n, 1.0f);
    BPack o;
    o.h[0] = __float2bfloat16(sum.x * inv);
    o.h[1] = __float2bfloat16(sum.y * inv);
    o.h[2] = __float2bfloat16(sum.z * inv);
    o.h[3] = __float2bfloat16(sum.w * inv);
    *(uint2*)(hmap + (size_t)cell * HID + tid * 4) = o.u;
}

// ---------------- map2token gather + dwskip + gelu + split -> A2, prefetch ----------------
__global__ __launch_bounds__(128) void gather_m2t_kernel(
    const __nv_bfloat16* __restrict__ hmap2,
    const int* __restrict__ off_n, const int* __restrict__ cnt_n,
    const int* __restrict__ vn_hw, const float* __restrict__ vn_w,
    const __nv_bfloat16* __restrict__ h, const float* __restrict__ skip,
    __nv_bfloat16* __restrict__ a2) {
    __shared__ int   s_hw[128];
    __shared__ float s_w [128];
    int tok = blockIdx.x;
    int b = tok >> 12;
    int tid = threadIdx.x;
    int start = off_n[tok];
    int n = cnt_n[tok];
    const int* vl = vn_hw + (size_t)b * N0;
    const float* wl = vn_w + (size_t)b * N0;
    float4 sum = make_float4(0.f, 0.f, 0.f, 0.f);
    float den = 0.f;
    for (int base = 0; base < n; base += 128) {
        int m = min(128, n - base);
        if (tid < m) {
            s_hw[tid] = vl[start + base + tid];
            s_w[tid]  = wl[start + base + tid];
        }
        __syncthreads();
        __nv_bfloat162 c0, c1;
        {
            const __nv_bfloat162* vp = (const __nv_bfloat162*)(hmap2 +
                ((size_t)b * HWSZ + s_hw[0]) * HID);
            c0 = vp[tid*2]; c1 = vp[tid*2+1];
        }
        for (int j = 0; j < m; j++) {
            __nv_bfloat162 n0, n1;
            if (j + 1 < m) {
                const __nv_bfloat162* vp = (const __nv_bfloat162*)(hmap2 +
                    ((size_t)b * HWSZ + s_hw[j+1]) * HID);
                n0 = vp[tid*2]; n1 = vp[tid*2+1];
            }
            float w = s_w[j];
            float2 f0 = __bfloat1622float2(c0);
            float2 f1 = __bfloat1622float2(c1);
            sum.x += w * f0.x; sum.y += w * f0.y; sum.z += w * f1.x; sum.w += w * f1.y;
            den += w;
            c0 = n0; c1 = n1;
        }
        __syncthreads();
    }
    float inv = 1.0f / fmaxf(den, 1e-6f);
    const __nv_bfloat162* hp = (const __nv_bfloat162*)(h + (size_t)tok * HID);
    __nv_bfloat162 h0 = hp[tid*2], h1 = hp[tid*2+1];
    float2 hf0 = __bfloat1622float2(h0);
    float2 hf1 = __bfloat1622float2(h1);
    float4 sk = ((const float4*)skip)[tid];
    float4 v;
    v.x = sum.x * inv + hf0.x * sk.x;
    v.y = sum.y * inv + hf0.y * sk.y;
    v.z = sum.z * inv + hf1.x * sk.z;
    v.w = sum.w * inv + hf1.y * sk.w;
    v.x = 0.5f * v.x * (1.0f + erff(v.x * 0.70710678118654752f));
    v.y = 0.5f * v.y * (1.0f + erff(v.y * 0.70710678118654752f));
    v.z = 0.5f * v.z * (1.0f + erff(v.z * 0.70710678118654752f));
    v.w = 0.5f * v.w * (1.0f + erff(v.w * 0.70710678118654752f));
    BPack hi, lo;
    split4(v, hi, lo);
    __nv_bfloat16* base2 = a2 + (size_t)tok * 1024;
    *(uint2*)(base2 + tid*4)        = hi.u;
    *(uint2*)(base2 + 512 + tid*4)  = lo.u;
}

__global__ void confp_kernel(const float* __restrict__ conf_map, float* __restrict__ confp) {
    int t = blockIdx.x * blockDim.x + threadIdx.x;
    if (t >= Bz * M2) return;
    int b = t >> 8;
    int p = t & 255;
    int oy = p >> 4, ox = p & 15;
    float s = 0.f;
    #pragma unroll
    for (int i = 0; i < 4; i++)
        #pragma unroll
        for (int j = 0; j < 4; j++)
            s += conf_map[b * HWSZ + (oy * 4 + i) * WW + (ox * 4 + j)];
    confp[t] = s * (1.0f / 16.0f);
}

// W [K][N] f32 -> W2 [2K][N] bf16: rows [whi | wlo]
__global__ void conv3_W_kernel(const float* __restrict__ in, __nv_bfloat16* __restrict__ out,
                               int K, int N) {
    int t = blockIdx.x * blockDim.x + threadIdx.x;
    int nq = N >> 2;
    if (t >= K * nq) return;
    int k = t / nq, n4 = t - k * nq;
    float4 v = ((const float4*)in)[t];
    BPack hi, lo;
    split4(v, hi, lo);
    *(uint2*)(out + (size_t)k*N + n4*4)        = hi.u;
    *(uint2*)(out + (size_t)(K + k)*N + n4*4)  = lo.u;
}

// ---------------- pipelined bf16 HMMA GEMM (3-stage, wrap-indexed 3-term) ----------------
#define AS_STRIDE 56
#define BS_STRIDE 136
#define AS_ELEMS  (128 * AS_STRIDE)
#define BS_ELEMS  (32 * BS_STRIDE)
#define HG_SMEM   (3 * (AS_ELEMS + BS_ELEMS) * 2)
__global__ __launch_bounds__(256, 2) void hgemm_kernel(
    const __nv_bfloat16* __restrict__ A, const __nv_bfloat16* __restrict__ B,
    const float* __restrict__ bias, const float* __restrict__ res,
    float* __restrict__ C, __nv_bfloat16* __restrict__ Cbf,
    int M, int N, int K, int KS) {
    extern __shared__ __align__(16) __nv_bfloat16 smbuf[];
    __nv_bfloat16* As0 = smbuf;
    __nv_bfloat16* Bs0 = smbuf + 3 * AS_ELEMS;
    int bm = blockIdx.y * 128;
    int bn = blockIdx.x * 128;
    int z  = blockIdx.z;
    int tid = threadIdx.x, lane = tid & 31, wid = tid >> 5;
    int wm = (wid >> 2) * 64, wn = (wid & 3) * 32;
    int K2 = 2 * K;

    float c[4][4][4];
    #pragma unroll
    for (int mt = 0; mt < 4; mt++)
        #pragma unroll
        for (int nt = 0; nt < 4; nt++)
            #pragma unroll
            for (int i = 0; i < 4; i++) c[mt][nt][i] = 0.f;

    int arow0 = tid >> 2, ach = tid & 3;
    int NIT = KS / 32;
    int kbase = z * KS;

    auto load_stage = [&](int st, int k0) {
        int ka = (k0 < K2) ? k0 : k0 - K2;
        int kb = (k0 < K)  ? k0 : k0 - K;
        __nv_bfloat16* Asp = As0 + st * AS_ELEMS;
        __nv_bfloat16* Bsp = Bs0 + st * BS_ELEMS;
        #pragma unroll
        for (int i = 0; i < 2; i++) {
            int row = arow0 + i * 64;
            cp16(&Asp[row * AS_STRIDE + ach * 8],
                 &A[(size_t)(bm + row) * K2 + ka + ach * 8]);
        }
        #pragma unroll
        for (int j = 0; j < 2; j++) {
            int idx = tid + j * 256;
            int row = idx >> 4, ch = idx & 15;
            cp16(&Bsp[row * BS_STRIDE + ch * 8],
                 &B[(size_t)(kb + row) * N + bn + ch * 8]);
        }
    };

    load_stage(0, kbase);
    CP_COMMIT();
    load_stage(1, kbase + 32);
    CP_COMMIT();

    for (int it = 0; it < NIT; it++) {
        CP_WAIT(1);
        __syncthreads();
        int st = it % 3;
        const __nv_bfloat16* Asp = As0 + st * AS_ELEMS;
        const __nv_bfloat16* Bsp = Bs0 + st * BS_ELEMS;
        #pragma unroll
        for (int ks = 0; ks < 2; ks++) {
            uint32_t a[4][4];
            #pragma unroll
            for (int mt = 0; mt < 4; mt++) {
                const void* p = &Asp[(wm + mt*16 + (lane & 15)) * AS_STRIDE + ks*16 + (lane >> 4) * 8];
                ldsm4(a[mt][0], a[mt][1], a[mt][2], a[mt][3], p);
            }
            uint32_t bfr[4][2];
            #pragma unroll
            for (int np = 0; np < 2; np++) {
                int g = lane >> 3, r = lane & 7;
                const void* p = &Bsp[(ks*16 + (g & 1)*8 + r) * BS_STRIDE + wn + np*16 + (g >> 1) * 8];
                uint32_t r0, r1, r2, r3;
                ldsm4t(r0, r1, r2, r3, p);
                bfr[np*2][0] = r0;   bfr[np*2][1] = r1;
                bfr[np*2+1][0] = r2; bfr[np*2+1][1] = r3;
            }
            #pragma unroll
            for (int mt = 0; mt < 4; mt++)
                #pragma unroll
                for (int nt = 0; nt < 4; nt++)
                    mma16816(c[mt][nt], a[mt], bfr[nt]);
        }
        __syncthreads();
        if (it + 2 < NIT) load_stage((it + 2) % 3, kbase + (it + 2) * 32);
        CP_COMMIT();
    }

    int r0 = lane >> 2, cc = (lane & 3) * 2;
    float* Cz = C ? (C + (size_t)z * M * N) : nullptr;
    #pragma unroll
    for (int mt = 0; mt < 4; mt++) {
        #pragma unroll
        for (int nt = 0; nt < 4; nt++) {
            int row = bm + wm + mt*16 + r0;
            int col = bn + wn + nt*8 + cc;
            float2 v0 = make_float2(c[mt][nt][0], c[mt][nt][1]);
            float2 v1 = make_float2(c[mt][nt][2], c[mt][nt][3]);
            if (bias) {
                float b0 = bias[col], b1 = bias[col+1];
                v0.x += b0; v0.y += b1; v1.x += b0; v1.y += b1;
            }
            size_t off0 = (size_t)row * N + col;
            size_t off1 = (size_t)(row + 8) * N + col;
            if (Cbf) {
                __nv_bfloat162 o0 = __floats2bfloat162_rn(v0.x, v0.y);
                __nv_bfloat162 o1 = __floats2bfloat162_rn(v1.x, v1.y);
                *(__nv_bfloat162*)(Cbf + off0) = o0;
                *(__nv_bfloat162*)(Cbf + off1) = o1;
            } else {
                if (res) {
                    float2 rr0 = *(const float2*)(res + off0);
                    float2 rr1 = *(const float2*)(res + off1);
                    v0.x += rr0.x; v0.y += rr0.y; v1.x += rr1.x; v1.y += rr1.y;
                }
                *(float2*)(Cz + off0) = v0;
                *(float2*)(Cz + off1) = v1;
            }
        }
    }
}

// ---------------- fused attention: unshifted softmax + f32x2, bf16 q, 256 thr ----------------
__global__ __launch_bounds__(256) void attn_kernel(
    const __nv_bfloat16* __restrict__ q, const float* __restrict__ kv,
    const float* __restrict__ confp, __nv_bfloat16* __restrict__ a2) {
    extern __shared__ float sm[];
    float* ks = sm;
    float* vs = sm + M2 * DH;
    float* cp = sm + 2 * M2 * DH;
    int bh = blockIdx.y;
    int b = bh >> 1, h = bh & 1;
    int tid = threadIdx.x;
    for (int t = tid; t < M2 * 16; t += 256) {
        int m = t >> 4, j4 = t & 15;
        const float* row = kv + ((size_t)(b * M2 + m)) * 256;
        ((float4*)ks)[m * 16 + j4] = ((const float4*)(row + h * DH))[j4];
        ((float4*)vs)[m * 16 + j4] = ((const float4*)(row + 128 + h * DH))[j4];
    }
    for (int t = tid; t < M2; t += 256) cp[t] = confp[b * M2 + t];
    __syncthreads();

    int n = blockIdx.x * 256 + tid;
    const __nv_bfloat162* qp = (const __nv_bfloat162*)(q + ((size_t)(b * NTOK + n)) * CC + h * DH);
    u64t q2[32];
    #pragma unroll
    for (int t = 0; t < 32; t++) {
        float2 f = __bfloat1622float2(qp[t]);
        q2[t] = pack2f(f.x * 0.125f, f.y * 0.125f);
    }
    u64t acc2[32];
    #pragma unroll
    for (int j = 0; j < 32; j++) acc2[j] = 0ULL;
    float l = 0.f;

    for (int m = 0; m < M2; m++) {
        const ulonglong2* kp = (const ulonglong2*)(ks + m * DH);
        u64t s0 = 0ULL, s1 = 0ULL, s2 = 0ULL, s3 = 0ULL;
        #pragma unroll
        for (int t = 0; t < 16; t += 2) {
            ulonglong2 k0 = kp[t];
            ulonglong2 k1 = kp[t+1];
            s0 = fma2(q2[2*t],   k0.x, s0);
            s1 = fma2(q2[2*t+1], k0.y, s1);
            s2 = fma2(q2[2*t+2], k1.x, s2);
            s3 = fma2(q2[2*t+3], k1.y, s3);
        }
        u64t st = add2(add2(s0, s1), add2(s2, s3));
        float slo, shi;
        unpack2(st, slo, shi);
        float p = __expf(slo + shi + cp[m]);
        l += p;
        u64t p2 = dup2(p);
        const ulonglong2* vp = (const ulonglong2*)(vs + m * DH);
        #pragma unroll
        for (int t = 0; t < 16; t++) {
            ulonglong2 vv = vp[t];
            acc2[2*t]   = fma2(p2, vv.x, acc2[2*t]);
            acc2[2*t+1] = fma2(p2, vv.y, acc2[2*t+1]);
        }
    }
    float inv = 1.0f / l;
    __nv_bfloat16* a2row = a2 + (size_t)(b * NTOK + n) * 256 + h * DH;
    #pragma unroll
    for (int t = 0; t < 16; t++) {
        float c0, c1, c2, c3;
        unpack2(acc2[2*t], c0, c1);
        unpack2(acc2[2*t+1], c2, c3);
        float4 o4 = make_float4(c0 * inv, c1 * inv, c2 * inv, c3 * inv);
        BPack hi, lo;
        split4(o4, hi, lo);
        *(uint2*)(a2row + t*4)        = hi.u;
        *(uint2*)(a2row + 128 + t*4)  = lo.u;
    }
}

// depthwise 3x3 SAME conv over (B,64,64,512), bf16 in / bf16 out
__global__ void dwconv_kernel(const __nv_bfloat16* __restrict__ hmap, const float* __restrict__ w,
                              const float* __restrict__ bias, __nv_bfloat16* __restrict__ out) {
    __shared__ float ws[9 * HID];
    __shared__ float bs[HID];
    int b = blockIdx.y, y = blockIdx.x;
    for (int t = threadIdx.x; t < 9 * HID; t += blockDim.x) ws[t] = w[t];
    for (int t = threadIdx.x; t < HID; t += blockDim.x) bs[t] = bias[t];
    __syncthreads();
    const __nv_bfloat16* base = hmap + ((size_t)b * HWSZ) * HID;
    __nv_bfloat16* ob = out + ((size_t)(b * HWSZ) + y * WW) * HID;
    const int H2 = HID / 2;
    for (int t = threadIdx.x; t < WW * H2; t += blockDim.x) {
        int x = t / H2;
        int c2 = t - x * H2;
        int c = c2 * 2;
        float accx = bs[c], accy = bs[c + 1];
        #pragma unroll
        for (int dy = -1; dy <= 1; dy++) {
            int yy = y + dy;
            if ((unsigned)yy >= HH) continue;
            #pragma unroll
            for (int dx = -1; dx <= 1; dx++) {
                int xx = x + dx;
                if ((unsigned)xx >= WW) continue;
                __nv_bfloat162 p = *(const __nv_bfloat162*)(base +
                    ((size_t)(yy * WW + xx)) * HID + c);
                float2 f = __bfloat1622float2(p);
                int wi = ((dy+1)*3 + dx+1) * HID + c;
                accx += f.x * ws[wi];
                accy += f.y * ws[wi + 1];
            }
        }
        *(__nv_bfloat162*)(ob + (size_t)x * HID + c) = __floats2bfloat162_rn(accx, accy);
    }
}

// ---------------- host helpers ----------------
static __nv_bfloat16 *s_a3, *s_w3;

static void hgemm_run(const float* W, const float* bias, const float* res,
                      float* C, __nv_bfloat16* Cbf, int M, int Nc, int K) {
    conv3_W_kernel<<<(K * Nc / 4 + 255) / 256, 256>>>(W, s_w3, K, Nc);
    cudaFuncSetAttribute(hgemm_kernel, cudaFuncAttributeMaxDynamicSharedMemorySize, HG_SMEM);
    dim3 grid(Nc / 128, M / 128, 1);
    hgemm_kernel<<<grid, 256, HG_SMEM>>>(s_a3, s_w3, bias, res, C, Cbf, M, Nc, K, 3 * K);
}

extern "C" void kernel_launch(void* const* d_in, const int* in_sizes, int n_in,
                              void* d_out, int out_size) {
    const float* x        = (const float*)d_in[0];
    const float* loc      = (const float*)d_in[1];
    const int*   idx_agg  = (const int*)  d_in[2];
    const float* aggw     = (const float*)d_in[3];
    const float* xsrc     = (const float*)d_in[4];
    const int*   idx_aggs = (const int*)  d_in[5];
    const float* confs    = (const float*)d_in[6];
    const float* ln1_g    = (const float*)d_in[7];
    const float* ln1_b    = (const float*)d_in[8];
    const float* ln2_g    = (const float*)d_in[9];
    const float* ln2_b    = (const float*)d_in[10];
    const float* wq       = (const float*)d_in[11];
    const float* wkv      = (const float*)d_in[12];
    const float* wproj    = (const float*)d_in[13];
    const float* bproj    = (const float*)d_in[14];
    const float* sr_w     = (const float*)d_in[15];
    const float* sr_b     = (const float*)d_in[16];
    const float* srn_g    = (const float*)d_in[17];
    const float* srn_b    = (const float*)d_in[18];
    const float* fc1_w    = (const float*)d_in[19];
    const float* fc1_b    = (const float*)d_in[20];
    const float* dw_w     = (const float*)d_in[21];
    const float* dw_b     = (const float*)d_in[22];
    const float* dwskip   = (const float*)d_in[23];
    const float* fc2_w    = (const float*)d_in[24];
    const float* fc2_b    = (const float*)d_in[25];
    float* out = (float*)d_out;

    float *p_confmap, *p_psum, *p_confp, *p_kv, *p_x1, *p_vn_w;
    __nv_bfloat16 *p_q, *p_h, *p_hmap, *p_hmap2;
    int *p_idx_hw, *p_cnt_hw, *p_off_hw, *p_cnt_n, *p_off_n,
        *p_vhw_src, *p_vhw_agg, *p_vn_hw;
    cudaGetSymbolAddress((void**)&p_q, g_q);
    cudaGetSymbolAddress((void**)&p_idx_hw, g_idx_hw);
    cudaGetSymbolAddress((void**)&p_cnt_hw, g_cnt_hw);
    cudaGetSymbolAddress((void**)&p_off_hw, g_off_hw);
    cudaGetSymbolAddress((void**)&p_cnt_n, g_cnt_n);
    cudaGetSymbolAddress((void**)&p_off_n, g_off_n);
    cudaGetSymbolAddress((void**)&p_vhw_src, g_vhw_src);
    cudaGetSymbolAddress((void**)&p_vhw_agg, g_vhw_agg);
    cudaGetSymbolAddress((void**)&p_vn_hw, g_vn_hw);
    cudaGetSymbolAddress((void**)&p_vn_w, g_vn_w);
    cudaGetSymbolAddress((void**)&p_confmap, g_confmap);
    cudaGetSymbolAddress((void**)&p_psum, g_psum);
    cudaGetSymbolAddress((void**)&p_confp, g_confp);
    cudaGetSymbolAddress((void**)&p_kv, g_kv);
    cudaGetSymbolAddress((void**)&p_x1, g_x1);
    cudaGetSymbolAddress((void**)&p_h, g_h);
    cudaGetSymbolAddress((void**)&p_hmap, g_hmap);
    cudaGetSymbolAddress((void**)&p_hmap2, g_hmap2);
    cudaGetSymbolAddress((void**)&s_a3, g_a3);
    cudaGetSymbolAddress((void**)&s_w3, g_w3);

    // 1. CSR build
    zero2_kernel<<<32, 256>>>(p_cnt_hw, p_cnt_n, Bz*HWSZ/4);
    gridcount_kernel<<<(Bz*N0 + 255) / 256, 256>>>(loc, idx_agg, p_idx_hw, p_cnt_hw, p_cnt_n);
    scanfill_kernel<<<16, 1024>>>(p_cnt_hw, p_off_hw, p_idx_hw, idx_aggs, idx_agg,
                                  p_vhw_src, p_vhw_agg,
                                  p_cnt_n, p_off_n, aggw, p_vn_hw, p_vn_w);

    // 2. token2map #1: warp-per-cell fused LN + im2col + split -> SR GEMM A2
    gather_t2m1_kernel<<<Bz*HWSZ/8, 256>>>(xsrc, confs, ln1_g, ln1_b,
                                           p_off_hw, p_cnt_hw, p_vhw_src,
                                           s_a3, p_confmap);

    // 3. SR conv: split-K HMMA directly on A2
    conv3_W_kernel<<<(2048*128/4 + 255) / 256, 256>>>(sr_w, s_w3, 2048, 128);
    {
        cudaFuncSetAttribute(hgemm_kernel, cudaFuncAttributeMaxDynamicSharedMemorySize, HG_SMEM);
        dim3 grid(1, 16, KSP);
        hgemm_kernel<<<grid, 256, HG_SMEM>>>(s_a3, s_w3, nullptr, nullptr, p_psum, nullptr,
                                             2048, 128, 2048, 6144 / KSP);
    }

    // 4. conf pooling
    confp_kernel<<<(Bz*M2 + 255) / 256, 256>>>(p_confmap, p_confp);

    // 5a. reduce+LN(srn)+split -> a2; wkv GEMM
    skred_ln_split_kernel<<<(2048 + 7) / 8, 256>>>(p_psum, sr_b, srn_g, srn_b, s_a3);
    hgemm_run(wkv, nullptr, nullptr, p_kv, nullptr, 2048, 256, 128);

    // 5b. LN(ln1,x)+split -> a2; wq GEMM (bf16 q out)
    ln_split_kernel<<<(Bz*NTOK + 7) / 8, 256>>>(x, ln1_g, ln1_b, s_a3, Bz*NTOK);
    hgemm_run(wq, nullptr, nullptr, nullptr, p_q, Bz*NTOK, 128, 128);

    // 6. fused attention
    {
        size_t smem = (2 * M2 * DH + M2) * sizeof(float);
        cudaFuncSetAttribute(attn_kernel, cudaFuncAttributeMaxDynamicSharedMemorySize, (int)smem);
        dim3 grid(NTOK / 256, Bz * NHEADS);
        attn_kernel<<<grid, 256, smem>>>(p_q, p_kv, p_confp, s_a3);
    }

    // 7. output projection + residual
    hgemm_run(wproj, bproj, x, p_x1, nullptr, Bz*NTOK, 128, 128);

    // 8. ln2+split + fc1 (bf16 h out)
    ln_split_kernel<<<(Bz*NTOK + 7) / 8, 256>>>(p_x1, ln2_g, ln2_b, s_a3, Bz*NTOK);
    hgemm_run(fc1_w, fc1_b, nullptr, nullptr, p_h, Bz*NTOK, 512, 128);

    // 9. token2map #2 (prefetch)
    gather_t2m2_kernel<<<Bz*HWSZ, 128>>>(p_h, p_off_hw, p_cnt_hw, p_vhw_agg, p_hmap);

    // 10. depthwise 3x3 SAME conv
    {
        dim3 grid(HH, Bz);
        dwconv_kernel<<<grid, 256>>>(p_hmap, dw_w, dw_b, p_hmap2);
    }

    // 11. map2token + dwskip + gelu + split -> a2 (prefetch)
    gather_m2t_kernel<<<Bz*NTOK, 128>>>(p_hmap2, p_off_n, p_cnt_n, p_vn_hw, p_vn_w,
                                        p_h, dwskip, s_a3);

    // 12. fc2 + residual -> output
    hgemm_run(fc2_w, fc2_b, p_x1, out, nullptr, Bz*NTOK, 128, 512);
}

// round 17
// speedup vs baseline: 1.1446x; 1.1129x over previous
#include <cuda_runtime.h>
#include <cuda_bf16.h>
#include <cstdint>
#include <math.h>

// ---------------- problem constants (fixed shapes) ----------------
#define Bz      8
#define NTOK    4096
#define N0      16384
#define NS      16384
#define CC      128
#define HH      64
#define WW      64
#define HWSZ    4096
#define NHEADS  2
#define DH      64
#define M2      256
#define HID     512
#define KSP     8        // split-K factor for SR conv GEMM

// ---------------- packed fp32x2 helpers (attention) ----------------
typedef unsigned long long u64t;
__device__ __forceinline__ u64t dup2(float a) {
    u64t r; asm("mov.b64 %0, {%1, %1};" : "=l"(r) : "f"(a)); return r;
}
__device__ __forceinline__ u64t pack2f(float lo, float hi) {
    u64t r; asm("mov.b64 %0, {%1, %2};" : "=l"(r) : "f"(lo), "f"(hi)); return r;
}
__device__ __forceinline__ void unpack2(u64t v, float& lo, float& hi) {
    asm("mov.b64 {%0, %1}, %2;" : "=f"(lo), "=f"(hi) : "l"(v));
}
__device__ __forceinline__ u64t fma2(u64t a, u64t b, u64t c) {
    u64t d; asm("fma.rn.f32x2 %0, %1, %2, %3;" : "=l"(d) : "l"(a), "l"(b), "l"(c)); return d;
}
__device__ __forceinline__ u64t mul2(u64t a, u64t b) {
    u64t d; asm("mul.rn.f32x2 %0, %1, %2;" : "=l"(d) : "l"(a), "l"(b)); return d;
}
__device__ __forceinline__ u64t add2(u64t a, u64t b) {
    u64t d; asm("add.rn.f32x2 %0, %1, %2;" : "=l"(d) : "l"(a), "l"(b)); return d;
}

// ---------------- mma / ldmatrix / cp.async helpers ----------------
__device__ __forceinline__ void ldsm4(uint32_t& r0, uint32_t& r1, uint32_t& r2, uint32_t& r3,
                                      const void* p) {
    unsigned addr = (unsigned)__cvta_generic_to_shared(p);
    asm volatile("ldmatrix.sync.aligned.m8n8.x4.shared.b16 {%0,%1,%2,%3}, [%4];"
                 : "=r"(r0), "=r"(r1), "=r"(r2), "=r"(r3) : "r"(addr) : "memory");
}
__device__ __forceinline__ void ldsm4t(uint32_t& r0, uint32_t& r1, uint32_t& r2, uint32_t& r3,
                                       const void* p) {
    unsigned addr = (unsigned)__cvta_generic_to_shared(p);
    asm volatile("ldmatrix.sync.aligned.m8n8.x4.trans.shared.b16 {%0,%1,%2,%3}, [%4];"
                 : "=r"(r0), "=r"(r1), "=r"(r2), "=r"(r3) : "r"(addr) : "memory");
}
__device__ __forceinline__ void mma16816(float c[4], const uint32_t a[4], const uint32_t b[2]) {
    asm volatile(
        "mma.sync.aligned.m16n8k16.row.col.f32.bf16.bf16.f32 "
        "{%0,%1,%2,%3}, {%4,%5,%6,%7}, {%8,%9}, {%0,%1,%2,%3};"
        : "+f"(c[0]), "+f"(c[1]), "+f"(c[2]), "+f"(c[3])
        : "r"(a[0]), "r"(a[1]), "r"(a[2]), "r"(a[3]), "r"(b[0]), "r"(b[1]));
}
__device__ __forceinline__ void cp16(void* smem, const void* gmem) {
    unsigned s = (unsigned)__cvta_generic_to_shared(smem);
    asm volatile("cp.async.cg.shared.global [%0], [%1], 16;" :: "r"(s), "l"(gmem) : "memory");
}
#define CP_COMMIT() asm volatile("cp.async.commit_group;" ::: "memory")
#define CP_WAIT(n)  asm volatile("cp.async.wait_group %0;" :: "n"(n) : "memory")

// ---------------- scratch (device globals; no allocation) ----------------
__device__ __align__(16) __nv_bfloat16 g_q [Bz*NTOK*CC];   // bf16 q
__device__ int   g_idx_hw [Bz*N0];

__device__ int   g_cnt_hw [Bz*HWSZ];
__device__ int   g_off_hw [Bz*HWSZ];
__device__ int   g_cnt_n  [Bz*NTOK];
__device__ int   g_off_n  [Bz*NTOK];
// value lists (CSR-ordered consumer data)
__device__ int   g_vhw_src[Bz*N0];
__device__ int   g_vhw_agg[Bz*N0];
__device__ int   g_vn_hw  [Bz*N0];
__device__ float g_vn_w   [Bz*N0];

__device__ float g_confmap[Bz*HWSZ];
__device__ float g_psum   [KSP*2048*CC];
__device__ float g_confp  [2048];
__device__ float g_kv     [2048*256];
__device__ float g_x1     [Bz*NTOK*CC];
__device__ __align__(16) __nv_bfloat16 g_h     [Bz*NTOK*HID];
__device__ __align__(16) __nv_bfloat16 g_hmap  [Bz*HWSZ*HID];
__device__ __align__(16) __nv_bfloat16 g_hmap2 [Bz*HWSZ*HID];

// bf16 split buffers: A2 max = 32768 x 1024 (fc2); W2 max = 4096 x 256
__device__ __align__(16) __nv_bfloat16 g_a3 [(size_t)32768*1024];
__device__ __align__(16) __nv_bfloat16 g_w3 [(size_t)4096*256];

// ---------------- utility ----------------
__global__ void zero2_kernel(int* __restrict__ p1, int* __restrict__ p2, int n4) {
    int i = blockIdx.x * blockDim.x + threadIdx.x;
    int stride = gridDim.x * blockDim.x;
    int4 z = make_int4(0, 0, 0, 0);
    for (; i < n4; i += stride) { ((int4*)p1)[i] = z; ((int4*)p2)[i] = z; }
}

// ---------------- f32 -> bf16 split helpers ----------------
union BPack { __nv_bfloat16 h[4]; uint2 u; };
__device__ __forceinline__ void split4(float4 v, BPack& hi, BPack& lo) {
    hi.h[0] = __float2bfloat16(v.x); lo.h[0] = __float2bfloat16(v.x - __bfloat162float(hi.h[0]));
    hi.h[1] = __float2bfloat16(v.y); lo.h[1] = __float2bfloat16(v.y - __bfloat162float(hi.h[1]));
    hi.h[2] = __float2bfloat16(v.z); lo.h[2] = __float2bfloat16(v.z - __bfloat162float(hi.h[2]));
    hi.h[3] = __float2bfloat16(v.w); lo.h[3] = __float2bfloat16(v.w - __bfloat162float(hi.h[3]));
}

// LayerNorm fused with 2-segment bf16 split: A2 row = [hi(128) | lo(128)]
__global__ void ln_split_kernel(const float* __restrict__ in, const float* __restrict__ g,
                                const float* __restrict__ b, __nv_bfloat16* __restrict__ a2,
                                int rows) {
    int row  = blockIdx.x * 8 + (threadIdx.x >> 5);
    int lane = threadIdx.x & 31;
    if (row >= rows) return;
    float4 v = ((const float4*)(in + (size_t)row * CC))[lane];
    float s = v.x + v.y + v.z + v.w;
    #pragma unroll
    for (int o = 16; o; o >>= 1) s += __shfl_xor_sync(0xffffffffu, s, o);
    float mean = s * (1.0f / CC);
    float dx = v.x - mean, dy = v.y - mean, dz = v.z - mean, dw = v.w - mean;
    float s2 = dx*dx + dy*dy + dz*dz + dw*dw;
    #pragma unroll
    for (int o = 16; o; o >>= 1) s2 += __shfl_xor_sync(0xffffffffu, s2, o);
    float rstd = rsqrtf(s2 * (1.0f / CC) + 1e-5f);
    float4 gg = ((const float4*)g)[lane];
    float4 bb = ((const float4*)b)[lane];
    float4 o4 = make_float4(dx*rstd*gg.x + bb.x, dy*rstd*gg.y + bb.y,
                            dz*rstd*gg.z + bb.z, dw*rstd*gg.w + bb.w);
    BPack hi, lo;
    split4(o4, hi, lo);
    __nv_bfloat16* base = a2 + (size_t)row * 256;
    *(uint2*)(base + lane*4)        = hi.u;
    *(uint2*)(base + 128 + lane*4)  = lo.u;
}

// split-K reduce + bias + LN(srn) + split (SR conv epilogue)
__global__ void skred_ln_split_kernel(const float* __restrict__ part,
                                      const float* __restrict__ bias,
                                      const float* __restrict__ g, const float* __restrict__ b,
                                      __nv_bfloat16* __restrict__ a2) {
    int row  = blockIdx.x * 8 + (threadIdx.x >> 5);
    int lane = threadIdx.x & 31;
    if (row >= 2048) return;
    const int MN = 2048 * CC;
    float4 v = make_float4(0.f, 0.f, 0.f, 0.f);
    #pragma unroll
    for (int zz = 0; zz < KSP; zz++) {
        float4 p = ((const float4*)(part + (size_t)zz * MN + (size_t)row * CC))[lane];
        v.x += p.x; v.y += p.y; v.z += p.z; v.w += p.w;
    }
    float4 bi = ((const float4*)bias)[lane];
    v.x += bi.x; v.y += bi.y; v.z += bi.z; v.w += bi.w;
    float s = v.x + v.y + v.z + v.w;
    #pragma unroll
    for (int o = 16; o; o >>= 1) s += __shfl_xor_sync(0xffffffffu, s, o);
    float mean = s * (1.0f / CC);
    float dx = v.x - mean, dy = v.y - mean, dz = v.z - mean, dw = v.w - mean;
    float s2 = dx*dx + dy*dy + dz*dz + dw*dw;
    #pragma unroll
    for (int o = 16; o; o >>= 1) s2 += __shfl_xor_sync(0xffffffffu, s2, o);
    float rstd = rsqrtf(s2 * (1.0f / CC) + 1e-5f);
    float4 gg = ((const float4*)g)[lane];
    float4 bb = ((const float4*)b)[lane];
    float4 o4 = make_float4(dx*rstd*gg.x + bb.x, dy*rstd*gg.y + bb.y,
                            dz*rstd*gg.z + bb.z, dw*rstd*gg.w + bb.w);
    BPack hi, lo;
    split4(o4, hi, lo);
    __nv_bfloat16* base = a2 + (size_t)row * 256;
    *(uint2*)(base + lane*4)        = hi.u;
    *(uint2*)(base + 128 + lane*4)  = lo.u;
}

// ---------------- CSR build ----------------
__global__ void gridcount_kernel(const float* __restrict__ loc, const int* __restrict__ idx_agg,
                                 int* __restrict__ idx_hw,
                                 int* __restrict__ cnt_hw, int* __restrict__ cnt_n) {
    int t = blockIdx.x * blockDim.x + threadIdx.x;
    if (t >= Bz * N0) return;
    int b = t >> 14;
    float2 l = ((const float2*)loc)[t];
    float lx = (fminf(fmaxf(l.x, -1.f), 1.f) + 1.f) * 0.5f;
    float ly = (fminf(fmaxf(l.y, -1.f), 1.f) + 1.f) * 0.5f;
    int xi = (int)rintf(lx * (WW - 1));
    int yi = (int)rintf(ly * (HH - 1));
    int ihw = yi * WW + xi;
    idx_hw[t] = ihw;
    atomicAdd(&cnt_hw[b * HWSZ + ihw], 1);
    atomicAdd(&cnt_n [b * NTOK + idx_agg[t]], 1);
}

__global__ __launch_bounds__(1024) void scanfill_kernel(
    const int* __restrict__ cnt_hw, int* __restrict__ off_hw,
    const int* __restrict__ idx_hw, const int* __restrict__ idx_aggs,
    const int* __restrict__ idx_agg,
    int* __restrict__ vhw_src, int* __restrict__ vhw_agg,
    const int* __restrict__ cnt_n, int* __restrict__ off_n,
    const float* __restrict__ aggw,
    int* __restrict__ vn_hw, float* __restrict__ vn_w) {
    __shared__ int sm[1024];
    __shared__ int scur[4096];
    int blk = blockIdx.x, t = threadIdx.x;
    bool is_hw = blk < Bz;
    int b = is_hw ? blk : blk - Bz;
    const int* cnt = is_hw ? cnt_hw : cnt_n;
    int* off = is_hw ? off_hw : off_n;
    const int* c = cnt + b * 4096;
    int v0 = c[t*4], v1 = c[t*4+1], v2 = c[t*4+2], v3 = c[t*4+3];
    int tot = v0 + v1 + v2 + v3;
    sm[t] = tot;
    __syncthreads();
    #pragma unroll
    for (int o = 1; o < 1024; o <<= 1) {
        int u = (t >= o) ? sm[t - o] : 0;
        __syncthreads();
        sm[t] += u;
        __syncthreads();
    }
    int base = sm[t] - tot;
    int* of = off + b * 4096;
    of[t*4]   = base;            scur[t*4]   = base;
    of[t*4+1] = base + v0;       scur[t*4+1] = base + v0;
    of[t*4+2] = base + v0+v1;    scur[t*4+2] = base + v0+v1;
    of[t*4+3] = base + v0+v1+v2; scur[t*4+3] = base + v0+v1+v2;
    __syncthreads();
    if (is_hw) {
        const int* kh = idx_hw  + (size_t)b * N0;
        const int* s1 = idx_aggs + (size_t)b * N0;
        const int* s2 = idx_agg  + (size_t)b * N0;
        int* o1 = vhw_src + (size_t)b * N0;
        int* o2 = vhw_agg + (size_t)b * N0;
        for (int p = t; p < N0; p += 1024) {
            int pos = atomicAdd(&scur[kh[p]], 1);
            o1[pos] = s1[p];
            o2[pos] = s2[p];
        }
    } else {
        const int* kn = idx_agg + (size_t)b * N0;
        const int* s1 = idx_hw  + (size_t)b * N0;
        const float* s2 = aggw  + (size_t)b * N0;
        int* o1 = vn_hw + (size_t)b * N0;
        float* o2 = vn_w + (size_t)b * N0;
        for (int p = t; p < N0; p += 1024) {
            int pos = atomicAdd(&scur[kn[p]], 1);
            o1[pos] = s1[p];
            o2[pos] = s2[p];
        }
    }
}

// ---------------- token2map #1: WARP-PER-CELL, fused LN + im2col + split ----------------
__global__ __launch_bounds__(256) void gather_t2m1_kernel(
    const float* __restrict__ xsrc, const float* __restrict__ confs,
    const float* __restrict__ ln_g, const float* __restrict__ ln_b,
    const int* __restrict__ off_hw, const int* __restrict__ cnt_hw,
    const int* __restrict__ vhw_src,
    __nv_bfloat16* __restrict__ a2, float* __restrict__ confmap) {
    int warp = threadIdx.x >> 5, lane = threadIdx.x & 31;
    int cell = blockIdx.x * 8 + warp;
    int b = cell >> 12;
    int start = off_hw[cell];
    int n = cnt_hw[cell];
    const int* vl = vhw_src + (size_t)b * N0;
    float4 gg = ((const float4*)ln_g)[lane];
    float4 bb = ((const float4*)ln_b)[lane];
    float4 acc = make_float4(0.f, 0.f, 0.f, 0.f);
    float cs = 0.f;
    float4 v;
    int i_cur = -1;
    if (n > 0) {
        i_cur = vl[start];
        v = ((const float4*)(xsrc + ((size_t)b * NS + i_cur) * CC))[lane];
    }
    for (int j = 0; j < n; j++) {
        float4 vn;
        int i_next = -1;
        if (j + 1 < n) {
            i_next = vl[start + j + 1];
            vn = ((const float4*)(xsrc + ((size_t)b * NS + i_next) * CC))[lane];
        }
        float s1 = v.x + v.y + v.z + v.w;
        float s2 = v.x*v.x + v.y*v.y + v.z*v.z + v.w*v.w;
        #pragma unroll
        for (int o = 16; o; o >>= 1) {
            s1 += __shfl_xor_sync(0xffffffffu, s1, o);
            s2 += __shfl_xor_sync(0xffffffffu, s2, o);
        }
        float mean = s1 * (1.0f / CC);
        float var  = s2 * (1.0f / CC) - mean * mean;
        float rstd = rsqrtf(var + 1e-5f);
        acc.x += (v.x - mean) * rstd * gg.x + bb.x;
        acc.y += (v.y - mean) * rstd * gg.y + bb.y;
        acc.z += (v.z - mean) * rstd * gg.z + bb.z;
        acc.w += (v.w - mean) * rstd * gg.w + bb.w;
        if (lane == 0) cs += confs[(size_t)b * NS + i_cur];
        v = vn;
        i_cur = i_next;
    }
    float inv = 1.0f / fmaxf((float)n, 1.0f);
    float4 o = make_float4(acc.x * inv, acc.y * inv, acc.z * inv, acc.w * inv);
    int yy = (cell >> 6) & 63, xx = cell & 63;
    int prow = b * 256 + (yy >> 2) * 16 + (xx >> 2);
    int colbase = ((yy & 3) * 4 + (xx & 3)) * 128;
    BPack hi, lo;
    split4(o, hi, lo);
    __nv_bfloat16* dst = a2 + (size_t)prow * 4096 + colbase + lane * 4;
    *(uint2*)dst          = hi.u;
    *(uint2*)(dst + 2048) = lo.u;
    if (lane == 0) confmap[cell] = cs * inv;
}

// ---------------- token2map #2: WARP-PER-CELL (bf16 h, 512ch) -> bf16 hmap ----------------
// lane owns 16 channels (2 x uint4 per 1KB row); sequential points, depth-1 prefetch.
__global__ __launch_bounds__(256) void gather_t2m2_kernel(
    const __nv_bfloat16* __restrict__ h,
    const int* __restrict__ off_hw, const int* __restrict__ cnt_hw,
    const int* __restrict__ vhw_agg, __nv_bfloat16* __restrict__ hmap) {
    int warp = threadIdx.x >> 5, lane = threadIdx.x & 31;
    int cell = blockIdx.x * 8 + warp;
    int b = cell >> 12;
    int start = off_hw[cell];
    int n = cnt_hw[cell];
    const int* vl = vhw_agg + (size_t)b * N0;
    float acc[16];
    #pragma unroll
    for (int k = 0; k < 16; k++) acc[k] = 0.f;
    uint4 c0, c1;
    if (n > 0) {
        const uint4* vp = (const uint4*)(h + ((size_t)b * NTOK + vl[start]) * HID);
        c0 = vp[lane*2]; c1 = vp[lane*2+1];
    }
    for (int j = 0; j < n; j++) {
        uint4 n0, n1;
        if (j + 1 < n) {
            const uint4* vp = (const uint4*)(h + ((size_t)b * NTOK + vl[start + j + 1]) * HID);
            n0 = vp[lane*2]; n1 = vp[lane*2+1];
        }
        const __nv_bfloat162* p0 = (const __nv_bfloat162*)&c0;
        const __nv_bfloat162* p1 = (const __nv_bfloat162*)&c1;
        #pragma unroll
        for (int k = 0; k < 4; k++) {
            float2 f0 = __bfloat1622float2(p0[k]);
            float2 f1 = __bfloat1622float2(p1[k]);
            acc[2*k]   += f0.x; acc[2*k+1]   += f0.y;
            acc[8+2*k] += f1.x; acc[8+2*k+1] += f1.y;
        }
        c0 = n0; c1 = n1;
    }
    float inv = 1.0f / fmaxf((float)n, 1.0f);
    __nv_bfloat162 ov[8];
    #pragma unroll
    for (int k = 0; k < 8; k++)
        ov[k] = __floats2bfloat162_rn(acc[2*k] * inv, acc[2*k+1] * inv);
    uint4* dst = (uint4*)(hmap + (size_t)cell * HID + lane * 16);
    dst[0] = *(uint4*)&ov[0];
    dst[1] = *(uint4*)&ov[4];
}

// ---------------- map2token: WARP-PER-TOKEN + dwskip + gelu + split -> A2 ----------------
__global__ __launch_bounds__(256) void gather_m2t_kernel(
    const __nv_bfloat16* __restrict__ hmap2,
    const int* __restrict__ off_n, const int* __restrict__ cnt_n,
    const int* __restrict__ vn_hw, const float* __restrict__ vn_w,
    const __nv_bfloat16* __restrict__ h, const float* __restrict__ skip,
    __nv_bfloat16* __restrict__ a2) {
    int warp = threadIdx.x >> 5, lane = threadIdx.x & 31;
    int tok = blockIdx.x * 8 + warp;
    int b = tok >> 12;
    int start = off_n[tok];
    int n = cnt_n[tok];
    const int* vl = vn_hw + (size_t)b * N0;
    const float* wl = vn_w + (size_t)b * N0;
    float acc[16];
    #pragma unroll
    for (int k = 0; k < 16; k++) acc[k] = 0.f;
    float den = 0.f;
    uint4 c0, c1;
    float wcur = 0.f;
    if (n > 0) {
        wcur = wl[start];
        const uint4* vp = (const uint4*)(hmap2 + ((size_t)b * HWSZ + vl[start]) * HID);
        c0 = vp[lane*2]; c1 = vp[lane*2+1];
    }
    for (int j = 0; j < n; j++) {
        uint4 n0, n1;
        float wnext = 0.f;
        if (j + 1 < n) {
            wnext = wl[start + j + 1];
            const uint4* vp = (const uint4*)(hmap2 + ((size_t)b * HWSZ + vl[start + j + 1]) * HID);
            n0 = vp[lane*2]; n1 = vp[lane*2+1];
        }
        const __nv_bfloat162* p0 = (const __nv_bfloat162*)&c0;
        const __nv_bfloat162* p1 = (const __nv_bfloat162*)&c1;
        #pragma unroll
        for (int k = 0; k < 4; k++) {
            float2 f0 = __bfloat1622float2(p0[k]);
            float2 f1 = __bfloat1622float2(p1[k]);
            acc[2*k]   += wcur * f0.x; acc[2*k+1]   += wcur * f0.y;
            acc[8+2*k] += wcur * f1.x; acc[8+2*k+1] += wcur * f1.y;
        }
        den += wcur;
        c0 = n0; c1 = n1; wcur = wnext;
    }
    float inv = 1.0f / fmaxf(den, 1e-6f);
    // h (dwskip residual) for this lane's 16 channels
    const uint4* hp = (const uint4*)(h + (size_t)tok * HID + lane * 16);
    uint4 h0 = hp[0], h1 = hp[1];
    const __nv_bfloat162* hq0 = (const __nv_bfloat162*)&h0;
    const __nv_bfloat162* hq1 = (const __nv_bfloat162*)&h1;
    __nv_bfloat16* base2 = a2 + (size_t)tok * 1024 + lane * 16;
    #pragma unroll
    for (int g = 0; g < 4; g++) {
        float4 sk = ((const float4*)skip)[lane * 4 + g];
        float2 hf0, hf1;
        if (g < 2) { hf0 = __bfloat1622float2(hq0[g*2]); hf1 = __bfloat1622float2(hq0[g*2+1]); }
        else       { hf0 = __bfloat1622float2(hq1[(g-2)*2]); hf1 = __bfloat1622float2(hq1[(g-2)*2+1]); }
        float4 v;
        v.x = acc[g*4+0] * inv + hf0.x * sk.x;
        v.y = acc[g*4+1] * inv + hf0.y * sk.y;
        v.z = acc[g*4+2] * inv + hf1.x * sk.z;
        v.w = acc[g*4+3] * inv + hf1.y * sk.w;
        v.x = 0.5f * v.x * (1.0f + erff(v.x * 0.70710678118654752f));
        v.y = 0.5f * v.y * (1.0f + erff(v.y * 0.70710678118654752f));
        v.z = 0.5f * v.z * (1.0f + erff(v.z * 0.70710678118654752f));
        v.w = 0.5f * v.w * (1.0f + erff(v.w * 0.70710678118654752f));
        BPack hi, lo;
        split4(v, hi, lo);
        *(uint2*)(base2 + g*4)        = hi.u;
        *(uint2*)(base2 + 512 + g*4)  = lo.u;
    }
}

__global__ void confp_kernel(const float* __restrict__ conf_map, float* __restrict__ confp) {
    int t = blockIdx.x * blockDim.x + threadIdx.x;
    if (t >= Bz * M2) return;
    int b = t >> 8;
    int p = t & 255;
    int oy = p >> 4, ox = p & 15;
    float s = 0.f;
    #pragma unroll
    for (int i = 0; i < 4; i++)
        #pragma unroll
        for (int j = 0; j < 4; j++)
            s += conf_map[b * HWSZ + (oy * 4 + i) * WW + (ox * 4 + j)];
    confp[t] = s * (1.0f / 16.0f);
}

// W [K][N] f32 -> W2 [2K][N] bf16: rows [whi | wlo]
__global__ void conv3_W_kernel(const float* __restrict__ in, __nv_bfloat16* __restrict__ out,
                               int K, int N) {
    int t = blockIdx.x * blockDim.x + threadIdx.x;
    int nq = N >> 2;
    if (t >= K * nq) return;
    int k = t / nq, n4 = t - k * nq;
    float4 v = ((const float4*)in)[t];
    BPack hi, lo;
    split4(v, hi, lo);
    *(uint2*)(out + (size_t)k*N + n4*4)        = hi.u;
    *(uint2*)(out + (size_t)(K + k)*N + n4*4)  = lo.u;
}

// ---------------- pipelined bf16 HMMA GEMM (3-stage, wrap-indexed 3-term) ----------------
#define AS_STRIDE 56
#define BS_STRIDE 136
#define AS_ELEMS  (128 * AS_STRIDE)
#define BS_ELEMS  (32 * BS_STRIDE)
#define HG_SMEM   (3 * (AS_ELEMS + BS_ELEMS) * 2)
__global__ __launch_bounds__(256, 2) void hgemm_kernel(
    const __nv_bfloat16* __restrict__ A, const __nv_bfloat16* __restrict__ B,
    const float* __restrict__ bias, const float* __restrict__ res,
    float* __restrict__ C, __nv_bfloat16* __restrict__ Cbf,
    int M, int N, int K, int KS) {
    extern __shared__ __align__(16) __nv_bfloat16 smbuf[];
    __nv_bfloat16* As0 = smbuf;
    __nv_bfloat16* Bs0 = smbuf + 3 * AS_ELEMS;
    int bm = blockIdx.y * 128;
    int bn = blockIdx.x * 128;
    int z  = blockIdx.z;
    int tid = threadIdx.x, lane = tid & 31, wid = tid >> 5;
    int wm = (wid >> 2) * 64, wn = (wid & 3) * 32;
    int K2 = 2 * K;

    float c[4][4][4];
    #pragma unroll
    for (int mt = 0; mt < 4; mt++)
        #pragma unroll
        for (int nt = 0; nt < 4; nt++)
            #pragma unroll
            for (int i = 0; i < 4; i++) c[mt][nt][i] = 0.f;

    int arow0 = tid >> 2, ach = tid & 3;
    int NIT = KS / 32;
    int kbase = z * KS;

    auto load_stage = [&](int st, int k0) {
        int ka = (k0 < K2) ? k0 : k0 - K2;
        int kb = (k0 < K)  ? k0 : k0 - K;
        __nv_bfloat16* Asp = As0 + st * AS_ELEMS;
        __nv_bfloat16* Bsp = Bs0 + st * BS_ELEMS;
        #pragma unroll
        for (int i = 0; i < 2; i++) {
            int row = arow0 + i * 64;
            cp16(&Asp[row * AS_STRIDE + ach * 8],
                 &A[(size_t)(bm + row) * K2 + ka + ach * 8]);
        }
        #pragma unroll
        for (int j = 0; j < 2; j++) {
            int idx = tid + j * 256;
            int row = idx >> 4, ch = idx & 15;
            cp16(&Bsp[row * BS_STRIDE + ch * 8],
                 &B[(size_t)(kb + row) * N + bn + ch * 8]);
        }
    };

    load_stage(0, kbase);
    CP_COMMIT();
    load_stage(1, kbase + 32);
    CP_COMMIT();

    for (int it = 0; it < NIT; it++) {
        CP_WAIT(1);
        __syncthreads();
        int st = it % 3;
        const __nv_bfloat16* Asp = As0 + st * AS_ELEMS;
        const __nv_bfloat16* Bsp = Bs0 + st * BS_ELEMS;
        #pragma unroll
        for (int ks = 0; ks < 2; ks++) {
            uint32_t a[4][4];
            #pragma unroll
            for (int mt = 0; mt < 4; mt++) {
                const void* p = &Asp[(wm + mt*16 + (lane & 15)) * AS_STRIDE + ks*16 + (lane >> 4) * 8];
                ldsm4(a[mt][0], a[mt][1], a[mt][2], a[mt][3], p);
            }
            uint32_t bfr[4][2];
            #pragma unroll
            for (int np = 0; np < 2; np++) {
                int g = lane >> 3, r = lane & 7;
                const void* p = &Bsp[(ks*16 + (g & 1)*8 + r) * BS_STRIDE + wn + np*16 + (g >> 1) * 8];
                uint32_t r0, r1, r2, r3;
                ldsm4t(r0, r1, r2, r3, p);
                bfr[np*2][0] = r0;   bfr[np*2][1] = r1;
                bfr[np*2+1][0] = r2; bfr[np*2+1][1] = r3;
            }
            #pragma unroll
            for (int mt = 0; mt < 4; mt++)
                #pragma unroll
                for (int nt = 0; nt < 4; nt++)
                    mma16816(c[mt][nt], a[mt], bfr[nt]);
        }
        __syncthreads();
        if (it + 2 < NIT) load_stage((it + 2) % 3, kbase + (it + 2) * 32);
        CP_COMMIT();
    }

    int r0 = lane >> 2, cc = (lane & 3) * 2;
    float* Cz = C ? (C + (size_t)z * M * N) : nullptr;
    #pragma unroll
    for (int mt = 0; mt < 4; mt++) {
        #pragma unroll
        for (int nt = 0; nt < 4; nt++) {
            int row = bm + wm + mt*16 + r0;
            int col = bn + wn + nt*8 + cc;
            float2 v0 = make_float2(c[mt][nt][0], c[mt][nt][1]);
            float2 v1 = make_float2(c[mt][nt][2], c[mt][nt][3]);
            if (bias) {
                float b0 = bias[col], b1 = bias[col+1];
                v0.x += b0; v0.y += b1; v1.x += b0; v1.y += b1;
            }
            size_t off0 = (size_t)row * N + col;
            size_t off1 = (size_t)(row + 8) * N + col;
            if (Cbf) {
                __nv_bfloat162 o0 = __floats2bfloat162_rn(v0.x, v0.y);
                __nv_bfloat162 o1 = __floats2bfloat162_rn(v1.x, v1.y);
                *(__nv_bfloat162*)(Cbf + off0) = o0;
                *(__nv_bfloat162*)(Cbf + off1) = o1;
            } else {
                if (res) {
                    float2 rr0 = *(const float2*)(res + off0);
                    float2 rr1 = *(const float2*)(res + off1);
                    v0.x += rr0.x; v0.y += rr0.y; v1.x += rr1.x; v1.y += rr1.y;
                }
                *(float2*)(Cz + off0) = v0;
                *(float2*)(Cz + off1) = v1;
            }
        }
    }
}

// ---------------- fused attention: unshifted softmax + f32x2, bf16 q, 256 thr ----------------
__global__ __launch_bounds__(256) void attn_kernel(
    const __nv_bfloat16* __restrict__ q, const float* __restrict__ kv,
    const float* __restrict__ confp, __nv_bfloat16* __restrict__ a2) {
    extern __shared__ float sm[];
    float* ks = sm;
    float* vs = sm + M2 * DH;
    float* cp = sm + 2 * M2 * DH;
    int bh = blockIdx.y;
    int b = bh >> 1, h = bh & 1;
    int tid = threadIdx.x;
    for (int t = tid; t < M2 * 16; t += 256) {
        int m = t >> 4, j4 = t & 15;
        const float* row = kv + ((size_t)(b * M2 + m)) * 256;
        ((float4*)ks)[m * 16 + j4] = ((const float4*)(row + h * DH))[j4];
        ((float4*)vs)[m * 16 + j4] = ((const float4*)(row + 128 + h * DH))[j4];
    }
    for (int t = tid; t < M2; t += 256) cp[t] = confp[b * M2 + t];
    __syncthreads();

    int n = blockIdx.x * 256 + tid;
    const __nv_bfloat162* qp = (const __nv_bfloat162*)(q + ((size_t)(b * NTOK + n)) * CC + h * DH);
    u64t q2[32];
    #pragma unroll
    for (int t = 0; t < 32; t++) {
        float2 f = __bfloat1622float2(qp[t]);
        q2[t] = pack2f(f.x * 0.125f, f.y * 0.125f);
    }
    u64t acc2[32];
    #pragma unroll
    for (int j = 0; j < 32; j++) acc2[j] = 0ULL;
    float l = 0.f;

    for (int m = 0; m < M2; m++) {
        const ulonglong2* kp = (const ulonglong2*)(ks + m * DH);
        u64t s0 = 0ULL, s1 = 0ULL, s2 = 0ULL, s3 = 0ULL;
        #pragma unroll
        for (int t = 0; t < 16; t += 2) {
            ulonglong2 k0 = kp[t];
            ulonglong2 k1 = kp[t+1];
            s0 = fma2(q2[2*t],   k0.x, s0);
            s1 = fma2(q2[2*t+1], k0.y, s1);
            s2 = fma2(q2[2*t+2], k1.x, s2);
            s3 = fma2(q2[2*t+3], k1.y, s3);
        }
        u64t st = add2(add2(s0, s1), add2(s2, s3));
        float slo, shi;
        unpack2(st, slo, shi);
        float p = __expf(slo + shi + cp[m]);
        l += p;
        u64t p2 = dup2(p);
        const ulonglong2* vp = (const ulonglong2*)(vs + m * DH);
        #pragma unroll
        for (int t = 0; t < 16; t++) {
            ulonglong2 vv = vp[t];
            acc2[2*t]   = fma2(p2, vv.x, acc2[2*t]);
            acc2[2*t+1] = fma2(p2, vv.y, acc2[2*t+1]);
        }
    }
    float inv = 1.0f / l;
    __nv_bfloat16* a2row = a2 + (size_t)(b * NTOK + n) * 256 + h * DH;
    #pragma unroll
    for (int t = 0; t < 16; t++) {
        float c0, c1, c2, c3;
        unpack2(acc2[2*t], c0, c1);
        unpack2(acc2[2*t+1], c2, c3);
        float4 o4 = make_float4(c0 * inv, c1 * inv, c2 * inv, c3 * inv);
        BPack hi, lo;
        split4(o4, hi, lo);
        *(uint2*)(a2row + t*4)        = hi.u;
        *(uint2*)(a2row + 128 + t*4)  = lo.u;
    }
}

// ---------------- depthwise 3x3 conv: register weights + sliding window ----------------
// block = (y, b); thread owns channel pair c = 2*tid; slides along x.
__global__ __launch_bounds__(256) void dwconv_kernel(
    const __nv_bfloat16* __restrict__ hmap, const float* __restrict__ w,
    const float* __restrict__ bias, __nv_bfloat16* __restrict__ out) {
    int b = blockIdx.y, y = blockIdx.x;
    int c = threadIdx.x * 2;
    float wr[3][3][2];
    #pragma unroll
    for (int dy = 0; dy < 3; dy++)
        #pragma unroll
        for (int dx = 0; dx < 3; dx++) {
            wr[dy][dx][0] = w[(dy*3 + dx) * HID + c];
            wr[dy][dx][1] = w[(dy*3 + dx) * HID + c + 1];
        }
    float b0 = bias[c], b1 = bias[c + 1];
    const __nv_bfloat16* rows[3];
    bool valid[3];
    #pragma unroll
    for (int r = 0; r < 3; r++) {
        int yy = y - 1 + r;
        valid[r] = (unsigned)yy < HH;
        rows[r] = hmap + ((size_t)b * HWSZ + yy * WW) * HID + c;
    }
    __nv_bfloat16* ob = out + ((size_t)b * HWSZ + y * WW) * HID + c;

    float2 win[3][3];
    #pragma unroll
    for (int r = 0; r < 3; r++) {
        win[r][0] = make_float2(0.f, 0.f);
        win[r][1] = valid[r] ? __bfloat1622float2(*(const __nv_bfloat162*)rows[r])
                             : make_float2(0.f, 0.f);
    }
    for (int x = 0; x < WW; x++) {
        #pragma unroll
        for (int r = 0; r < 3; r++) {
            win[r][2] = (valid[r] && x + 1 < WW)
                ? __bfloat1622float2(*(const __nv_bfloat162*)(rows[r] + (size_t)(x + 1) * HID))
                : make_float2(0.f, 0.f);
        }
        float ax = b0, ay = b1;
        #pragma unroll
        for (int r = 0; r < 3; r++)
            #pragma unroll
            for (int d = 0; d < 3; d++) {
                ax += win[r][d].x * wr[r][d][0];
                ay += win[r][d].y * wr[r][d][1];
            }
        *(__nv_bfloat162*)(ob + (size_t)x * HID) = __floats2bfloat162_rn(ax, ay);
        #pragma unroll
        for (int r = 0; r < 3; r++) {
            win[r][0] = win[r][1];
            win[r][1] = win[r][2];
        }
    }
}

// ---------------- host helpers ----------------
static __nv_bfloat16 *s_a3, *s_w3;

static void hgemm_run(const float* W, const float* bias, const float* res,
                      float* C, __nv_bfloat16* Cbf, int M, int Nc, int K) {
    conv3_W_kernel<<<(K * Nc / 4 + 255) / 256, 256>>>(W, s_w3, K, Nc);
    cudaFuncSetAttribute(hgemm_kernel, cudaFuncAttributeMaxDynamicSharedMemorySize, HG_SMEM);
    dim3 grid(Nc / 128, M / 128, 1);
    hgemm_kernel<<<grid, 256, HG_SMEM>>>(s_a3, s_w3, bias, res, C, Cbf, M, Nc, K, 3 * K);
}

extern "C" void kernel_launch(void* const* d_in, const int* in_sizes, int n_in,
                              void* d_out, int out_size) {
    const float* x        = (const float*)d_in[0];
    const float* loc      = (const float*)d_in[1];
    const int*   idx_agg  = (const int*)  d_in[2];
    const float* aggw     = (const float*)d_in[3];
    const float* xsrc     = (const float*)d_in[4];
    const int*   idx_aggs = (const int*)  d_in[5];
    const float* confs    = (const float*)d_in[6];
    const float* ln1_g    = (const float*)d_in[7];
    const float* ln1_b    = (const float*)d_in[8];
    const float* ln2_g    = (const float*)d_in[9];
    const float* ln2_b    = (const float*)d_in[10];
    const float* wq       = (const float*)d_in[11];
    const float* wkv      = (const float*)d_in[12];
    const float* wproj    = (const float*)d_in[13];
    const float* bproj    = (const float*)d_in[14];
    const float* sr_w     = (const float*)d_in[15];
    const float* sr_b     = (const float*)d_in[16];
    const float* srn_g    = (const float*)d_in[17];
    const float* srn_b    = (const float*)d_in[18];
    const float* fc1_w    = (const float*)d_in[19];
    const float* fc1_b    = (const float*)d_in[20];
    const float* dw_w     = (const float*)d_in[21];
    const float* dw_b     = (const float*)d_in[22];
    const float* dwskip   = (const float*)d_in[23];
    const float* fc2_w    = (const float*)d_in[24];
    const float* fc2_b    = (const float*)d_in[25];
    float* out = (float*)d_out;

    float *p_confmap, *p_psum, *p_confp, *p_kv, *p_x1, *p_vn_w;
    __nv_bfloat16 *p_q, *p_h, *p_hmap, *p_hmap2;
    int *p_idx_hw, *p_cnt_hw, *p_off_hw, *p_cnt_n, *p_off_n,
        *p_vhw_src, *p_vhw_agg, *p_vn_hw;
    cudaGetSymbolAddress((void**)&p_q, g_q);
    cudaGetSymbolAddress((void**)&p_idx_hw, g_idx_hw);
    cudaGetSymbolAddress((void**)&p_cnt_hw, g_cnt_hw);
    cudaGetSymbolAddress((void**)&p_off_hw, g_off_hw);
    cudaGetSymbolAddress((void**)&p_cnt_n, g_cnt_n);
    cudaGetSymbolAddress((void**)&p_off_n, g_off_n);
    cudaGetSymbolAddress((void**)&p_vhw_src, g_vhw_src);
    cudaGetSymbolAddress((void**)&p_vhw_agg, g_vhw_agg);
    cudaGetSymbolAddress((void**)&p_vn_hw, g_vn_hw);
    cudaGetSymbolAddress((void**)&p_vn_w, g_vn_w);
    cudaGetSymbolAddress((void**)&p_confmap, g_confmap);
    cudaGetSymbolAddress((void**)&p_psum, g_psum);
    cudaGetSymbolAddress((void**)&p_confp, g_confp);
    cudaGetSymbolAddress((void**)&p_kv, g_kv);
    cudaGetSymbolAddress((void**)&p_x1, g_x1);
    cudaGetSymbolAddress((void**)&p_h, g_h);
    cudaGetSymbolAddress((void**)&p_hmap, g_hmap);
    cudaGetSymbolAddress((void**)&p_hmap2, g_hmap2);
    cudaGetSymbolAddress((void**)&s_a3, g_a3);
    cudaGetSymbolAddress((void**)&s_w3, g_w3);

    // 1. CSR build
    zero2_kernel<<<32, 256>>>(p_cnt_hw, p_cnt_n, Bz*HWSZ/4);
    gridcount_kernel<<<(Bz*N0 + 255) / 256, 256>>>(loc, idx_agg, p_idx_hw, p_cnt_hw, p_cnt_n);
    scanfill_kernel<<<16, 1024>>>(p_cnt_hw, p_off_hw, p_idx_hw, idx_aggs, idx_agg,
                                  p_vhw_src, p_vhw_agg,
                                  p_cnt_n, p_off_n, aggw, p_vn_hw, p_vn_w);

    // 2. token2map #1: warp-per-cell fused LN + im2col + split -> SR GEMM A2
    gather_t2m1_kernel<<<Bz*HWSZ/8, 256>>>(xsrc, confs, ln1_g, ln1_b,
                                           p_off_hw, p_cnt_hw, p_vhw_src,
                                           s_a3, p_confmap);

    // 3. SR conv: split-K HMMA directly on A2
    conv3_W_kernel<<<(2048*128/4 + 255) / 256, 256>>>(sr_w, s_w3, 2048, 128);
    {
        cudaFuncSetAttribute(hgemm_kernel, cudaFuncAttributeMaxDynamicSharedMemorySize, HG_SMEM);
        dim3 grid(1, 16, KSP);
        hgemm_kernel<<<grid, 256, HG_SMEM>>>(s_a3, s_w3, nullptr, nullptr, p_psum, nullptr,
                                             2048, 128, 2048, 6144 / KSP);
    }

    // 4. conf pooling
    confp_kernel<<<(Bz*M2 + 255) / 256, 256>>>(p_confmap, p_confp);

    // 5a. reduce+LN(srn)+split -> a2; wkv GEMM
    skred_ln_split_kernel<<<(2048 + 7) / 8, 256>>>(p_psum, sr_b, srn_g, srn_b, s_a3);
    hgemm_run(wkv, nullptr, nullptr, p_kv, nullptr, 2048, 256, 128);

    // 5b. LN(ln1,x)+split -> a2; wq GEMM (bf16 q out)
    ln_split_kernel<<<(Bz*NTOK + 7) / 8, 256>>>(x, ln1_g, ln1_b, s_a3, Bz*NTOK);
    hgemm_run(wq, nullptr, nullptr, nullptr, p_q, Bz*NTOK, 128, 128);

    // 6. fused attention
    {
        size_t smem = (2 * M2 * DH + M2) * sizeof(float);
        cudaFuncSetAttribute(attn_kernel, cudaFuncAttributeMaxDynamicSharedMemorySize, (int)smem);
        dim3 grid(NTOK / 256, Bz * NHEADS);
        attn_kernel<<<grid, 256, smem>>>(p_q, p_kv, p_confp, s_a3);
    }

    // 7. output projection + residual
    hgemm_run(wproj, bproj, x, p_x1, nullptr, Bz*NTOK, 128, 128);

    // 8. ln2+split + fc1 (bf16 h out)
    ln_split_kernel<<<(Bz*NTOK + 7) / 8, 256>>>(p_x1, ln2_g, ln2_b, s_a3, Bz*NTOK);
    hgemm_run(fc1_w, fc1_b, nullptr, nullptr, p_h, Bz*NTOK, 512, 128);

    // 9. token2map #2: warp-per-cell
    gather_t2m2_kernel<<<Bz*HWSZ/8, 256>>>(p_h, p_off_hw, p_cnt_hw, p_vhw_agg, p_hmap);

    // 10. depthwise 3x3 SAME conv (register weights, sliding window)
    {
        dim3 grid(HH, Bz);
        dwconv_kernel<<<grid, 256>>>(p_hmap, dw_w, dw_b, p_hmap2);
    }

    // 11. map2token: warp-per-token + dwskip + gelu + split -> a2
    gather_m2t_kernel<<<Bz*NTOK/8, 256>>>(p_hmap2, p_off_n, p_cnt_n, p_vn_hw, p_vn_w,
                                          p_h, dwskip, s_a3);

    // 12. fc2 + residual -> output
    hgemm_run(fc2_w, fc2_b, p_x1, out, nullptr, Bz*NTOK, 128, 512);
}